// round 2
// baseline (speedup 1.0000x reference)
#include <cuda_runtime.h>
#include <cstdint>

// Problem constants (fixed by the reference)
#define NN   50000
#define MM   25000
#define NNZV 800000
#define F_IN 128
#define HIDC 256
#define F_OUT 128

// ---------------------------------------------------------------------------
// Scratch carved out of one big __device__ array (no allocations allowed).
// All kernels resolve pointers from this symbol in DEVICE code; kernel_launch
// contains kernel launches only (no runtime API calls at all).
// ---------------------------------------------------------------------------
constexpr size_t SZ_X1  = (size_t)NN * HIDC * 4;     // x @ W1
constexpr size_t SZ_E1  = (size_t)MM * HIDC * 4;     // edge features L1
constexpr size_t SZ_H   = (size_t)NN * HIDC * 4;     // elu(out1 + b1)
constexpr size_t SZ_X2  = (size_t)NN * F_OUT * 4;    // h @ W2
constexpr size_t SZ_DEGN = (size_t)NN * 4;
constexpr size_t SZ_DEGM = (size_t)MM * 4;
constexpr size_t SZ_OFFN = (size_t)NN * 4;
constexpr size_t SZ_OFFM = (size_t)MM * 4;
constexpr size_t SZ_CURN = (size_t)NN * 4;
constexpr size_t SZ_CURM = (size_t)MM * 4;
constexpr size_t SZ_DINV = (size_t)NN * 4;
constexpr size_t SZ_BINV = (size_t)MM * 4;
constexpr size_t SZ_NE   = (size_t)NNZV * 4;         // node -> list of edges
constexpr size_t SZ_EN   = (size_t)NNZV * 4;         // edge -> list of nodes

constexpr size_t OFF_X1   = 0;
constexpr size_t OFF_E1   = OFF_X1 + SZ_X1;
constexpr size_t OFF_H    = OFF_E1 + SZ_E1;
constexpr size_t OFF_X2   = OFF_H + SZ_H;
constexpr size_t OFF_DEGN = OFF_X2 + SZ_X2;
constexpr size_t OFF_DEGM = OFF_DEGN + SZ_DEGN;
constexpr size_t OFF_OFFN = OFF_DEGM + SZ_DEGM;
constexpr size_t OFF_OFFM = OFF_OFFN + SZ_OFFN;
constexpr size_t OFF_CURN = OFF_OFFM + SZ_OFFM;
constexpr size_t OFF_CURM = OFF_CURN + SZ_CURN;
constexpr size_t OFF_DINV = OFF_CURM + SZ_CURM;
constexpr size_t OFF_BINV = OFF_DINV + SZ_DINV;
constexpr size_t OFF_NE   = OFF_BINV + SZ_BINV;
constexpr size_t OFF_EN   = OFF_NE + SZ_NE;
constexpr size_t SCRATCH_TOTAL = OFF_EN + SZ_EN;

__device__ __align__(256) unsigned char g_scratch[SCRATCH_TOTAL];

__device__ __forceinline__ float* scrF(size_t off) {
    return reinterpret_cast<float*>(g_scratch + off);
}
__device__ __forceinline__ int* scrI(size_t off) {
    return reinterpret_cast<int*>(g_scratch + off);
}

// ---------------------------------------------------------------------------
// CSR build kernels
// ---------------------------------------------------------------------------
__global__ void zero_deg_kernel() {
    int i = blockIdx.x * blockDim.x + threadIdx.x;
    int* degN = scrI(OFF_DEGN);
    int* degM = scrI(OFF_DEGM);
    if (i < NN) degN[i] = 0;
    if (i < MM) degM[i] = 0;
}

__global__ void count_deg_kernel(const int* __restrict__ node_idx,
                                 const int* __restrict__ edge_idx) {
    int* degN = scrI(OFF_DEGN);
    int* degM = scrI(OFF_DEGM);
    int stride = gridDim.x * blockDim.x;
    for (int i = blockIdx.x * blockDim.x + threadIdx.x; i < NNZV; i += stride) {
        atomicAdd(&degN[node_idx[i]], 1);
        atomicAdd(&degM[edge_idx[i]], 1);
    }
}

// Single-block exclusive scan + 1/deg. (deg/off/cur/inv given as byte offsets)
__global__ void scan_build_kernel(size_t degOff, size_t offOff, size_t curOff,
                                  size_t invOff, int n) {
    const int* deg = scrI(degOff);
    int* off = scrI(offOff);
    int* cur = scrI(curOff);
    float* inv = scrF(invOff);

    __shared__ int ssum[1024];
    int tid = threadIdx.x;
    int chunk = (n + 1023) >> 10;
    int start = tid * chunk;
    int end = min(start + chunk, n);
    int s = 0;
    for (int i = start; i < end; i++) s += deg[i];
    ssum[tid] = s;
    __syncthreads();
    // inclusive Hillis-Steele scan
    for (int d = 1; d < 1024; d <<= 1) {
        int v = (tid >= d) ? ssum[tid - d] : 0;
        __syncthreads();
        ssum[tid] += v;
        __syncthreads();
    }
    int run = (tid == 0) ? 0 : ssum[tid - 1];
    for (int i = start; i < end; i++) {
        off[i] = run;
        cur[i] = run;
        int d = deg[i];
        run += d;
        inv[i] = (d > 0) ? (1.0f / (float)d) : 0.0f;
    }
}

__global__ void fill_csr_kernel(const int* __restrict__ node_idx,
                                const int* __restrict__ edge_idx) {
    int* curN = scrI(OFF_CURN);
    int* curM = scrI(OFF_CURM);
    int* nodeEdges = scrI(OFF_NE);
    int* edgeNodes = scrI(OFF_EN);
    int stride = gridDim.x * blockDim.x;
    for (int i = blockIdx.x * blockDim.x + threadIdx.x; i < NNZV; i += stride) {
        int n = node_idx[i];
        int m = edge_idx[i];
        int p = atomicAdd(&curN[n], 1);
        nodeEdges[p] = m;
        int q = atomicAdd(&curM[m], 1);
        edgeNodes[q] = n;
    }
}

// ---------------------------------------------------------------------------
// Register-tiled fp32 GEMM: C[M,N] = A[M,K] @ B[K,N]
// BM=BN=64, BK=32, TM=TN=4, 256 threads. K % 32 == 0, N % 64 == 0 assumed.
// A and C addressed either via external pointers or scratch offsets:
// pass ptr != nullptr to use it, else the byte offset into g_scratch.
// ---------------------------------------------------------------------------
__global__ __launch_bounds__(256) void gemm64_kernel(
    const float* Aext, size_t aOff,
    const float* __restrict__ B,
    float* Cext, size_t cOff,
    int Mrows, int K, int Ncols)
{
    const float* __restrict__ A = Aext ? Aext : scrF(aOff);
    float* __restrict__ C = Cext ? Cext : scrF(cOff);

    __shared__ float As[32][68];   // padded, transposed: As[k][m]
    __shared__ float Bs[32][64];

    int tid = threadIdx.x;
    int tx = tid & 15;       // 0..15, N direction
    int ty = tid >> 4;       // 0..15, M direction
    int rowBase = blockIdx.y * 64;
    int colBase = blockIdx.x * 64;

    int aRow  = tid >> 3;    // 0..31
    int aCol4 = tid & 7;     // 0..7  (float4 granules in BK)
    int bRow  = tid >> 4;    // 0..15
    int bCol4 = tid & 15;    // 0..15 (float4 granules in BN)

    float acc[4][4] = {};

    for (int k0 = 0; k0 < K; k0 += 32) {
        #pragma unroll
        for (int r = 0; r < 2; r++) {
            int m = aRow + r * 32;
            int gm = rowBase + m;
            float4 v = make_float4(0.f, 0.f, 0.f, 0.f);
            if (gm < Mrows)
                v = *(const float4*)&A[(size_t)gm * K + k0 + aCol4 * 4];
            As[aCol4 * 4 + 0][m] = v.x;
            As[aCol4 * 4 + 1][m] = v.y;
            As[aCol4 * 4 + 2][m] = v.z;
            As[aCol4 * 4 + 3][m] = v.w;
        }
        #pragma unroll
        for (int r = 0; r < 2; r++) {
            int kk = bRow + r * 16;
            float4 v = *(const float4*)&B[(size_t)(k0 + kk) * Ncols + colBase + bCol4 * 4];
            *(float4*)&Bs[kk][bCol4 * 4] = v;
        }
        __syncthreads();
        #pragma unroll
        for (int k = 0; k < 32; k++) {
            float4 a4 = *(const float4*)&As[k][ty * 4];
            float4 b4 = *(const float4*)&Bs[k][tx * 4];
            float a[4] = {a4.x, a4.y, a4.z, a4.w};
            float b[4] = {b4.x, b4.y, b4.z, b4.w};
            #pragma unroll
            for (int i = 0; i < 4; i++)
                #pragma unroll
                for (int j = 0; j < 4; j++)
                    acc[i][j] += a[i] * b[j];
        }
        __syncthreads();
    }

    #pragma unroll
    for (int i = 0; i < 4; i++) {
        int gm = rowBase + ty * 4 + i;
        if (gm < Mrows) {
            float4 v = make_float4(acc[i][0], acc[i][1], acc[i][2], acc[i][3]);
            *(float4*)&C[(size_t)gm * Ncols + colBase + tx * 4] = v;
        }
    }
}

// ---------------------------------------------------------------------------
// Segment gather-reduce: dst[row,:] = inv[row] * sum_{j in CSR(row)} src[idx,:]
// Optional + bias, optional ELU. One row per threadIdx.y group, float4 per tx.
// src/dst given as (external ptr, scratch offset) pairs; CSR arrays via
// scratch offsets. Index loads are group-uniform -> L1 broadcast.
// ---------------------------------------------------------------------------
template<int C, bool HAS_BIAS, bool HAS_ELU>
__global__ void gather_rows_kernel(const float4* srcExt, size_t srcOff,
                                   float4* dstExt, size_t dstOff,
                                   size_t offOff, size_t degOff,
                                   size_t lstOff, size_t invOff,
                                   const float* __restrict__ bias,
                                   int nrows)
{
    constexpr int V = C / 4;
    const float4* __restrict__ src =
        srcExt ? srcExt : reinterpret_cast<const float4*>(g_scratch + srcOff);
    float4* __restrict__ dst =
        dstExt ? dstExt : reinterpret_cast<float4*>(g_scratch + dstOff);
    const int* __restrict__ off = scrI(offOff);
    const int* __restrict__ deg = scrI(degOff);
    const int* __restrict__ lst = scrI(lstOff);
    const float* __restrict__ inv = scrF(invOff);

    int row = blockIdx.x * blockDim.y + threadIdx.y;
    if (row >= nrows) return;
    int tx = threadIdx.x;      // 0..V-1
    int o = off[row];
    int d = deg[row];

    float ax = 0.f, ay = 0.f, az = 0.f, aw = 0.f;
    int j = 0;
    for (; j + 4 <= d; j += 4) {
        int i0 = __ldg(&lst[o + j + 0]);
        int i1 = __ldg(&lst[o + j + 1]);
        int i2 = __ldg(&lst[o + j + 2]);
        int i3 = __ldg(&lst[o + j + 3]);
        float4 v0 = __ldg(&src[(size_t)i0 * V + tx]);
        float4 v1 = __ldg(&src[(size_t)i1 * V + tx]);
        float4 v2 = __ldg(&src[(size_t)i2 * V + tx]);
        float4 v3 = __ldg(&src[(size_t)i3 * V + tx]);
        ax += (v0.x + v1.x) + (v2.x + v3.x);
        ay += (v0.y + v1.y) + (v2.y + v3.y);
        az += (v0.z + v1.z) + (v2.z + v3.z);
        aw += (v0.w + v1.w) + (v2.w + v3.w);
    }
    for (; j < d; j++) {
        int i0 = __ldg(&lst[o + j]);
        float4 v0 = __ldg(&src[(size_t)i0 * V + tx]);
        ax += v0.x; ay += v0.y; az += v0.z; aw += v0.w;
    }

    float s = inv[row];
    float4 r = make_float4(ax * s, ay * s, az * s, aw * s);
    if (HAS_BIAS) {
        float4 b = __ldg(&((const float4*)bias)[tx]);
        r.x += b.x; r.y += b.y; r.z += b.z; r.w += b.w;
    }
    if (HAS_ELU) {
        r.x = (r.x > 0.f) ? r.x : expm1f(r.x);
        r.y = (r.y > 0.f) ? r.y : expm1f(r.y);
        r.z = (r.z > 0.f) ? r.z : expm1f(r.z);
        r.w = (r.w > 0.f) ? r.w : expm1f(r.w);
    }
    dst[(size_t)row * V + tx] = r;
}

// ---------------------------------------------------------------------------
// Launch: kernel launches ONLY (no runtime API calls).
// ---------------------------------------------------------------------------
extern "C" void kernel_launch(void* const* d_in, const int* in_sizes, int n_in,
                              void* d_out, int out_size)
{
    const float* x        = (const float*)d_in[0];   // [N, 128]
    const float* W1       = (const float*)d_in[1];   // [128, 256]
    const float* b1       = (const float*)d_in[2];   // [256]
    const float* W2       = (const float*)d_in[3];   // [256, 128]
    const float* b2       = (const float*)d_in[4];   // [128]
    const int*   node_idx = (const int*)d_in[5];     // [800000]
    const int*   edge_idx = (const int*)d_in[6];     // [800000]

    float* out   = (float*)d_out;                    // [N, 128]
    float* e_out = out + (size_t)NN * F_OUT;         // [M, 128]

    // ---- CSR build ----
    zero_deg_kernel<<<(NN + 255) / 256, 256>>>();
    count_deg_kernel<<<2048, 256>>>(node_idx, edge_idx);
    scan_build_kernel<<<1, 1024>>>(OFF_DEGN, OFF_OFFN, OFF_CURN, OFF_DINV, NN);
    scan_build_kernel<<<1, 1024>>>(OFF_DEGM, OFF_OFFM, OFF_CURM, OFF_BINV, MM);
    fill_csr_kernel<<<2048, 256>>>(node_idx, edge_idx);

    // ---- Layer 1 ----
    // x1 = x @ W1   [50000,128] x [128,256]
    {
        dim3 grid(HIDC / 64, (NN + 63) / 64);
        gemm64_kernel<<<grid, 256>>>(x, 0, W1, nullptr, OFF_X1, NN, F_IN, HIDC);
    }
    // e1[m] = Binv[m] * sum_{n in edge m} x1[n]
    {
        dim3 blk(HIDC / 4, 4);  // (64,4) = 256 threads
        gather_rows_kernel<HIDC, false, false><<<(MM + 3) / 4, blk>>>(
            nullptr, OFF_X1, nullptr, OFF_E1,
            OFF_OFFM, OFF_DEGM, OFF_EN, OFF_BINV, nullptr, MM);
    }
    // h[n] = elu(Dinv[n] * sum_{m in node n} e1[m] + b1)
    {
        dim3 blk(HIDC / 4, 4);
        gather_rows_kernel<HIDC, true, true><<<(NN + 3) / 4, blk>>>(
            nullptr, OFF_E1, nullptr, OFF_H,
            OFF_OFFN, OFF_DEGN, OFF_NE, OFF_DINV, b1, NN);
    }

    // ---- Layer 2 ----
    // x2 = h @ W2   [50000,256] x [256,128]
    {
        dim3 grid(F_OUT / 64, (NN + 63) / 64);
        gemm64_kernel<<<grid, 256>>>(nullptr, OFF_H, W2, nullptr, OFF_X2,
                                     NN, HIDC, F_OUT);
    }
    // e_out[m] = Binv[m] * sum x2[n]   (this is the returned `e`)
    {
        dim3 blk(F_OUT / 4, 8);  // (32,8) = 256 threads
        gather_rows_kernel<F_OUT, false, false><<<(MM + 7) / 8, blk>>>(
            nullptr, OFF_X2, (float4*)e_out, 0,
            OFF_OFFM, OFF_DEGM, OFF_EN, OFF_BINV, nullptr, MM);
    }
    // out[n] = Dinv[n] * sum_{m in node n} e_out[m] + b2
    {
        dim3 blk(F_OUT / 4, 8);
        gather_rows_kernel<F_OUT, true, false><<<(NN + 7) / 8, blk>>>(
            (const float4*)e_out, 0, (float4*)out, 0,
            OFF_OFFN, OFF_DEGN, OFF_NE, OFF_DINV, b2, NN);
    }
}

// round 3
// speedup vs baseline: 1.4520x; 1.4520x over previous
#include <cuda_runtime.h>
#include <cstdint>

#define NN   50000
#define MM   25000
#define NNZV 800000
#define F_IN 128
#define HIDC 256
#define F_OUT 128

// ---------------------------------------------------------------------------
// Scratch (single __device__ array; pointers resolved in device code only).
// ---------------------------------------------------------------------------
constexpr size_t SZ_T1   = (size_t)MM * F_IN * 4;    // S_M(B*x)        [M,128]
constexpr size_t SZ_T2   = (size_t)NN * F_IN * 4;    // S_N(D*t1)       [N,128]
constexpr size_t SZ_H    = (size_t)NN * HIDC * 4;    // elu(t2@W1+b1)   [N,256]
constexpr size_t SZ_X2   = (size_t)NN * F_OUT * 4;   // h@W2            [N,128]
constexpr size_t SZ_DEGN = (size_t)NN * 4;
constexpr size_t SZ_DEGM = (size_t)MM * 4;
constexpr size_t SZ_OFFN = (size_t)NN * 4;
constexpr size_t SZ_OFFM = (size_t)MM * 4;
constexpr size_t SZ_CURN = (size_t)NN * 4;
constexpr size_t SZ_CURM = (size_t)MM * 4;
constexpr size_t SZ_DINV = (size_t)NN * 4;
constexpr size_t SZ_BINV = (size_t)MM * 4;
constexpr size_t SZ_NE   = (size_t)NNZV * 4;
constexpr size_t SZ_EN   = (size_t)NNZV * 4;
constexpr size_t SZ_BS   = 256 * 4;   // block sums
constexpr size_t SZ_BP   = 256 * 4;   // block prefixes

constexpr size_t OFF_T1   = 0;
constexpr size_t OFF_T2   = OFF_T1 + SZ_T1;
constexpr size_t OFF_H    = OFF_T2 + SZ_T2;
constexpr size_t OFF_X2   = OFF_H + SZ_H;
constexpr size_t OFF_DEGN = OFF_X2 + SZ_X2;
constexpr size_t OFF_DEGM = OFF_DEGN + SZ_DEGN;   // contiguous after DEGN
constexpr size_t OFF_OFFN = OFF_DEGM + SZ_DEGM;
constexpr size_t OFF_OFFM = OFF_OFFN + SZ_OFFN;
constexpr size_t OFF_CURN = OFF_OFFM + SZ_OFFM;
constexpr size_t OFF_CURM = OFF_CURN + SZ_CURN;
constexpr size_t OFF_DINV = OFF_CURM + SZ_CURM;
constexpr size_t OFF_BINV = OFF_DINV + SZ_DINV;
constexpr size_t OFF_NE   = OFF_BINV + SZ_BINV;
constexpr size_t OFF_EN   = OFF_NE + SZ_NE;
constexpr size_t OFF_BS   = OFF_EN + SZ_EN;
constexpr size_t OFF_BP   = OFF_BS + SZ_BS;
constexpr size_t SCRATCH_TOTAL = OFF_BP + SZ_BP;

__device__ __align__(256) unsigned char g_scratch[SCRATCH_TOTAL];

__device__ __forceinline__ float* scrF(size_t off) {
    return reinterpret_cast<float*>(g_scratch + off);
}
__device__ __forceinline__ int* scrI(size_t off) {
    return reinterpret_cast<int*>(g_scratch + off);
}

// ---------------------------------------------------------------------------
// CSR build
// ---------------------------------------------------------------------------
__global__ void zero_deg_kernel() {
    int i = blockIdx.x * blockDim.x + threadIdx.x;
    int* degN = scrI(OFF_DEGN);
    int* degM = scrI(OFF_DEGM);
    if (i < NN) degN[i] = 0;
    if (i < MM) degM[i] = 0;
}

__global__ void count_deg_kernel(const int* __restrict__ node_idx,
                                 const int* __restrict__ edge_idx) {
    int* degN = scrI(OFF_DEGN);
    int* degM = scrI(OFF_DEGM);
    int stride = gridDim.x * blockDim.x;
    for (int i = blockIdx.x * blockDim.x + threadIdx.x; i < NNZV; i += stride) {
        atomicAdd(&degN[node_idx[i]], 1);
        atomicAdd(&degM[edge_idx[i]], 1);
    }
}

// Hierarchical scan over BOTH deg arrays (N segment then M segment).
constexpr int SC_ELEMS = 1024;                       // elems per block
constexpr int NBLK_N = (NN + SC_ELEMS - 1) / SC_ELEMS;   // 49
constexpr int NBLK_M = (MM + SC_ELEMS - 1) / SC_ELEMS;   // 25
constexpr int NBLK_T = NBLK_N + NBLK_M;                  // 74

// Phase A: per-block sums of deg.
__global__ __launch_bounds__(256) void scanA_kernel() {
    int blk = blockIdx.x;
    const int* deg;
    int n, b;
    if (blk < NBLK_N) { deg = scrI(OFF_DEGN); n = NN; b = blk; }
    else              { deg = scrI(OFF_DEGM); n = MM; b = blk - NBLK_N; }
    int tid = threadIdx.x;
    int base = b * SC_ELEMS + tid * 4;
    int s = 0;
    #pragma unroll
    for (int j = 0; j < 4; j++) {
        int i = base + j;
        if (i < n) s += deg[i];
    }
    // block reduce
    __shared__ int wsum[8];
    for (int d2 = 16; d2 > 0; d2 >>= 1) s += __shfl_down_sync(0xffffffffu, s, d2);
    if ((tid & 31) == 0) wsum[tid >> 5] = s;
    __syncthreads();
    if (tid < 8) {
        int v = wsum[tid];
        for (int d2 = 4; d2 > 0; d2 >>= 1) v += __shfl_down_sync(0xffu, v, d2);
        if (tid == 0) scrI(OFF_BS)[blk] = v;
    }
}

// Phase B: segmented exclusive scan of the 74 block sums (one small block).
__global__ void scanB_kernel() {
    __shared__ int sh[128];
    int tid = threadIdx.x;
    const int* bs = scrI(OFF_BS);
    sh[tid] = (tid < NBLK_T) ? bs[tid] : 0;
    __syncthreads();
    for (int d = 1; d < 128; d <<= 1) {
        int v = (tid >= d) ? sh[tid - d] : 0;
        __syncthreads();
        sh[tid] += v;
        __syncthreads();
    }
    if (tid < NBLK_T) {
        int pre = (tid == 0) ? 0 : sh[tid - 1];
        if (tid >= NBLK_N) pre -= sh[NBLK_N - 1];   // restart at M segment
        scrI(OFF_BP)[tid] = pre;
    }
}

// Phase C: write off/cur/inv with intra-block exclusive scan.
__global__ __launch_bounds__(256) void scanC_kernel() {
    int blk = blockIdx.x;
    const int* deg; int* off; int* cur; float* inv;
    int n, b;
    if (blk < NBLK_N) {
        deg = scrI(OFF_DEGN); off = scrI(OFF_OFFN); cur = scrI(OFF_CURN);
        inv = scrF(OFF_DINV); n = NN; b = blk;
    } else {
        deg = scrI(OFF_DEGM); off = scrI(OFF_OFFM); cur = scrI(OFF_CURM);
        inv = scrF(OFF_BINV); n = MM; b = blk - NBLK_N;
    }
    int tid = threadIdx.x;
    int base = b * SC_ELEMS + tid * 4;
    int d[4];
    int s = 0;
    #pragma unroll
    for (int j = 0; j < 4; j++) {
        int i = base + j;
        d[j] = (i < n) ? deg[i] : 0;
        s += d[j];
    }
    __shared__ int sh[256];
    sh[tid] = s;
    __syncthreads();
    for (int dd = 1; dd < 256; dd <<= 1) {
        int v = (tid >= dd) ? sh[tid - dd] : 0;
        __syncthreads();
        sh[tid] += v;
        __syncthreads();
    }
    int run = scrI(OFF_BP)[blk] + ((tid == 0) ? 0 : sh[tid - 1]);
    #pragma unroll
    for (int j = 0; j < 4; j++) {
        int i = base + j;
        if (i < n) {
            off[i] = run;
            cur[i] = run;
            inv[i] = (d[j] > 0) ? (1.0f / (float)d[j]) : 0.0f;
            run += d[j];
        }
    }
}

__global__ void fill_csr_kernel(const int* __restrict__ node_idx,
                                const int* __restrict__ edge_idx) {
    int* curN = scrI(OFF_CURN);
    int* curM = scrI(OFF_CURM);
    int* nodeEdges = scrI(OFF_NE);
    int* edgeNodes = scrI(OFF_EN);
    int stride = gridDim.x * blockDim.x;
    for (int i = blockIdx.x * blockDim.x + threadIdx.x; i < NNZV; i += stride) {
        int n = node_idx[i];
        int m = edge_idx[i];
        int p = atomicAdd(&curN[n], 1);
        nodeEdges[p] = m;
        int q = atomicAdd(&curM[m], 1);
        edgeNodes[q] = n;
    }
}

// ---------------------------------------------------------------------------
// 128x128 register-tiled fp32 GEMM, BK=8, 8x8 per thread, 256 threads.
// C = A[M,K] @ B[K,N], optional bias + ELU epilogue.
// K % 8 == 0, N % 128 == 0 assumed.
// ---------------------------------------------------------------------------
template<bool HAS_BIAS, bool HAS_ELU>
__global__ __launch_bounds__(256) void gemm128_kernel(
    const float* Aext, size_t aOff,
    const float* __restrict__ B,
    float* Cext, size_t cOff,
    const float* __restrict__ bias,
    int Mrows, int K, int Ncols)
{
    const float* __restrict__ A = Aext ? Aext : scrF(aOff);
    float* __restrict__ C = Cext ? Cext : scrF(cOff);

    __shared__ float As[8][132];   // transposed [k][m], padded
    __shared__ float Bs[8][128];

    int tid = threadIdx.x;
    int tx = tid & 15;             // N direction (8 cols each)
    int ty = tid >> 4;             // M direction (8 rows each)
    int rowBase = blockIdx.y * 128;
    int colBase = blockIdx.x * 128;

    int aRow = tid >> 1;           // 0..127
    int aK4  = tid & 1;            // 0..1 (float4 granule in BK=8)
    int bK   = tid >> 5;           // 0..7
    int bC4  = tid & 31;           // 0..31 (float4 granule in 128 cols)

    float acc[8][8] = {};

    for (int k0 = 0; k0 < K; k0 += 8) {
        int gm = rowBase + aRow;
        float4 va = make_float4(0.f, 0.f, 0.f, 0.f);
        if (gm < Mrows)
            va = *(const float4*)&A[(size_t)gm * K + k0 + aK4 * 4];
        As[aK4 * 4 + 0][aRow] = va.x;
        As[aK4 * 4 + 1][aRow] = va.y;
        As[aK4 * 4 + 2][aRow] = va.z;
        As[aK4 * 4 + 3][aRow] = va.w;

        float4 vb = *(const float4*)&B[(size_t)(k0 + bK) * Ncols + colBase + bC4 * 4];
        *(float4*)&Bs[bK][bC4 * 4] = vb;
        __syncthreads();

        #pragma unroll
        for (int k = 0; k < 8; k++) {
            float4 a0 = *(const float4*)&As[k][ty * 8];
            float4 a1 = *(const float4*)&As[k][ty * 8 + 4];
            float4 b0 = *(const float4*)&Bs[k][tx * 8];
            float4 b1 = *(const float4*)&Bs[k][tx * 8 + 4];
            float a[8] = {a0.x, a0.y, a0.z, a0.w, a1.x, a1.y, a1.z, a1.w};
            float b[8] = {b0.x, b0.y, b0.z, b0.w, b1.x, b1.y, b1.z, b1.w};
            #pragma unroll
            for (int i = 0; i < 8; i++)
                #pragma unroll
                for (int j = 0; j < 8; j++)
                    acc[i][j] += a[i] * b[j];
        }
        __syncthreads();
    }

    float bb[8];
    if (HAS_BIAS) {
        float4 c0 = __ldg(&((const float4*)&bias[colBase])[tx * 2]);
        float4 c1 = __ldg(&((const float4*)&bias[colBase])[tx * 2 + 1]);
        bb[0]=c0.x; bb[1]=c0.y; bb[2]=c0.z; bb[3]=c0.w;
        bb[4]=c1.x; bb[5]=c1.y; bb[6]=c1.z; bb[7]=c1.w;
    }

    #pragma unroll
    for (int i = 0; i < 8; i++) {
        int gm = rowBase + ty * 8 + i;
        if (gm < Mrows) {
            float r[8];
            #pragma unroll
            for (int j = 0; j < 8; j++) {
                float v = acc[i][j];
                if (HAS_BIAS) v += bb[j];
                if (HAS_ELU)  v = (v > 0.f) ? v : expm1f(v);
                r[j] = v;
            }
            float* cp = &C[(size_t)gm * Ncols + colBase + tx * 8];
            *(float4*)cp       = make_float4(r[0], r[1], r[2], r[3]);
            *(float4*)(cp + 4) = make_float4(r[4], r[5], r[6], r[7]);
        }
    }
}

// ---------------------------------------------------------------------------
// Segment gather-reduce (C=128): dst[row] = inv[row]*sum src[idx] (+bias)
// ---------------------------------------------------------------------------
template<bool HAS_BIAS>
__global__ void gather_rows_kernel(const float4* srcExt, size_t srcOff,
                                   float4* dstExt, size_t dstOff,
                                   size_t offOff, size_t degOff,
                                   size_t lstOff, size_t invOff,
                                   const float* __restrict__ bias,
                                   int nrows)
{
    constexpr int V = 32;   // 128 floats / 4
    const float4* __restrict__ src =
        srcExt ? srcExt : reinterpret_cast<const float4*>(g_scratch + srcOff);
    float4* __restrict__ dst =
        dstExt ? dstExt : reinterpret_cast<float4*>(g_scratch + dstOff);
    const int* __restrict__ off = scrI(offOff);
    const int* __restrict__ deg = scrI(degOff);
    const int* __restrict__ lst = scrI(lstOff);
    const float* __restrict__ inv = scrF(invOff);

    int row = blockIdx.x * blockDim.y + threadIdx.y;
    if (row >= nrows) return;
    int tx = threadIdx.x;   // 0..31
    int o = off[row];
    int d = deg[row];

    float ax = 0.f, ay = 0.f, az = 0.f, aw = 0.f;
    int j = 0;
    for (; j + 4 <= d; j += 4) {
        int i0 = __ldg(&lst[o + j + 0]);
        int i1 = __ldg(&lst[o + j + 1]);
        int i2 = __ldg(&lst[o + j + 2]);
        int i3 = __ldg(&lst[o + j + 3]);
        float4 v0 = __ldg(&src[(size_t)i0 * V + tx]);
        float4 v1 = __ldg(&src[(size_t)i1 * V + tx]);
        float4 v2 = __ldg(&src[(size_t)i2 * V + tx]);
        float4 v3 = __ldg(&src[(size_t)i3 * V + tx]);
        ax += (v0.x + v1.x) + (v2.x + v3.x);
        ay += (v0.y + v1.y) + (v2.y + v3.y);
        az += (v0.z + v1.z) + (v2.z + v3.z);
        aw += (v0.w + v1.w) + (v2.w + v3.w);
    }
    for (; j < d; j++) {
        int i0 = __ldg(&lst[o + j]);
        float4 v0 = __ldg(&src[(size_t)i0 * V + tx]);
        ax += v0.x; ay += v0.y; az += v0.z; aw += v0.w;
    }

    float s = inv[row];
    float4 r = make_float4(ax * s, ay * s, az * s, aw * s);
    if (HAS_BIAS) {
        float4 b = __ldg(&((const float4*)bias)[tx]);
        r.x += b.x; r.y += b.y; r.z += b.z; r.w += b.w;
    }
    dst[(size_t)row * V + tx] = r;
}

// ---------------------------------------------------------------------------
// Launch: kernel launches ONLY.
// ---------------------------------------------------------------------------
extern "C" void kernel_launch(void* const* d_in, const int* in_sizes, int n_in,
                              void* d_out, int out_size)
{
    const float* x        = (const float*)d_in[0];   // [N, 128]
    const float* W1       = (const float*)d_in[1];   // [128, 256]
    const float* b1       = (const float*)d_in[2];   // [256]
    const float* W2       = (const float*)d_in[3];   // [256, 128]
    const float* b2       = (const float*)d_in[4];   // [128]
    const int*   node_idx = (const int*)d_in[5];
    const int*   edge_idx = (const int*)d_in[6];

    float* out   = (float*)d_out;                    // [N, 128]
    float* e_out = out + (size_t)NN * F_OUT;         // [M, 128]

    // ---- CSR build ----
    zero_deg_kernel<<<(NN + 255) / 256, 256>>>();
    count_deg_kernel<<<2048, 256>>>(node_idx, edge_idx);
    scanA_kernel<<<NBLK_T, 256>>>();
    scanB_kernel<<<1, 128>>>();
    scanC_kernel<<<NBLK_T, 256>>>();
    fill_csr_kernel<<<2048, 256>>>(node_idx, edge_idx);

    dim3 gblk(32, 8);   // 256 threads, 8 rows/block

    // ---- Layer 1 (GEMM commuted past both segment-sums) ----
    // t1[m] = Binv[m] * sum_{n in edge m} x[n]
    gather_rows_kernel<false><<<(MM + 7) / 8, gblk>>>(
        (const float4*)x, 0, nullptr, OFF_T1,
        OFF_OFFM, OFF_DEGM, OFF_EN, OFF_BINV, nullptr, MM);
    // t2[n] = Dinv[n] * sum_{m in node n} t1[m]
    gather_rows_kernel<false><<<(NN + 7) / 8, gblk>>>(
        nullptr, OFF_T1, nullptr, OFF_T2,
        OFF_OFFN, OFF_DEGN, OFF_NE, OFF_DINV, nullptr, NN);
    // h = elu(t2 @ W1 + b1)   [50000,128]x[128,256]
    {
        dim3 grid(HIDC / 128, (NN + 127) / 128);
        gemm128_kernel<true, true><<<grid, 256>>>(
            nullptr, OFF_T2, W1, nullptr, OFF_H, b1, NN, F_IN, HIDC);
    }

    // ---- Layer 2 ----
    // x2 = h @ W2   [50000,256]x[256,128]
    {
        dim3 grid(F_OUT / 128, (NN + 127) / 128);
        gemm128_kernel<false, false><<<grid, 256>>>(
            nullptr, OFF_H, W2, nullptr, OFF_X2, nullptr, NN, HIDC, F_OUT);
    }
    // e_out[m] = Binv[m] * sum_{n in edge m} x2[n]   (returned `e`)
    gather_rows_kernel<false><<<(MM + 7) / 8, gblk>>>(
        nullptr, OFF_X2, (float4*)e_out, 0,
        OFF_OFFM, OFF_DEGM, OFF_EN, OFF_BINV, nullptr, MM);
    // out[n] = Dinv[n] * sum_{m in node n} e_out[m] + b2
    gather_rows_kernel<true><<<(NN + 7) / 8, gblk>>>(
        (const float4*)e_out, 0, (float4*)out, 0,
        OFF_OFFN, OFF_DEGN, OFF_NE, OFF_DINV, b2, NN);
}

// round 6
// speedup vs baseline: 1.5165x; 1.0444x over previous
#include <cuda_runtime.h>
#include <cuda_fp16.h>
#include <cstdint>

#define NN   50000
#define MM   25000
#define NNZV 800000
#define F_IN 128
#define HIDC 256
#define F_OUT 128

// ---------------------------------------------------------------------------
// Scratch (single __device__ array; resolved in device code only)
// ---------------------------------------------------------------------------
constexpr size_t SZ_XH   = (size_t)NN * F_IN * 2;    // x as fp16
constexpr size_t SZ_T1H  = (size_t)MM * F_IN * 2;    // gather1 out (fp16)
constexpr size_t SZ_T2   = (size_t)NN * F_IN * 4;    // gather2 out (fp32)
constexpr size_t SZ_H    = (size_t)NN * HIDC * 4;    // elu(t2@W1+b1) fp32
constexpr size_t SZ_X2H  = (size_t)NN * F_OUT * 2;   // h@W2 (fp16)
constexpr size_t SZ_EH   = (size_t)MM * F_OUT * 2;   // e as fp16
constexpr size_t SZ_DEGN = (size_t)NN * 4;
constexpr size_t SZ_DEGM = (size_t)MM * 4;
constexpr size_t SZ_OFFN = (size_t)NN * 4;
constexpr size_t SZ_OFFM = (size_t)MM * 4;
constexpr size_t SZ_CURN = (size_t)NN * 4;
constexpr size_t SZ_CURM = (size_t)MM * 4;
constexpr size_t SZ_DINV = (size_t)NN * 4;
constexpr size_t SZ_BINV = (size_t)MM * 4;
constexpr size_t SZ_NE   = (size_t)NNZV * 4;
constexpr size_t SZ_EN   = (size_t)NNZV * 4;
constexpr size_t SZ_BS   = 256 * 4;
constexpr size_t SZ_BP   = 256 * 4;

constexpr size_t OFF_XH   = 0;
constexpr size_t OFF_T1H  = OFF_XH + SZ_XH;
constexpr size_t OFF_T2   = OFF_T1H + SZ_T1H;
constexpr size_t OFF_H    = OFF_T2 + SZ_T2;
constexpr size_t OFF_X2H  = OFF_H + SZ_H;
constexpr size_t OFF_EH   = OFF_X2H + SZ_X2H;
constexpr size_t OFF_DEGN = OFF_EH + SZ_EH;
constexpr size_t OFF_DEGM = OFF_DEGN + SZ_DEGN;
constexpr size_t OFF_OFFN = OFF_DEGM + SZ_DEGM;
constexpr size_t OFF_OFFM = OFF_OFFN + SZ_OFFN;
constexpr size_t OFF_CURN = OFF_OFFM + SZ_OFFM;
constexpr size_t OFF_CURM = OFF_CURN + SZ_CURN;
constexpr size_t OFF_DINV = OFF_CURM + SZ_CURM;
constexpr size_t OFF_BINV = OFF_DINV + SZ_DINV;
constexpr size_t OFF_NE   = OFF_BINV + SZ_BINV;
constexpr size_t OFF_EN   = OFF_NE + SZ_NE;
constexpr size_t OFF_BS   = OFF_EN + SZ_EN;
constexpr size_t OFF_BP   = OFF_BS + SZ_BS;
constexpr size_t SCRATCH_TOTAL = OFF_BP + SZ_BP;

__device__ __align__(256) unsigned char g_scratch[SCRATCH_TOTAL];

__device__ __forceinline__ float* scrF(size_t off) {
    return reinterpret_cast<float*>(g_scratch + off);
}
__device__ __forceinline__ int* scrI(size_t off) {
    return reinterpret_cast<int*>(g_scratch + off);
}
__device__ __forceinline__ __half* scrH(size_t off) {
    return reinterpret_cast<__half*>(g_scratch + off);
}

// ---------------------------------------------------------------------------
// CSR build
// ---------------------------------------------------------------------------
__global__ void zero_deg_kernel() {
    int i = blockIdx.x * blockDim.x + threadIdx.x;
    int* degN = scrI(OFF_DEGN);
    int* degM = scrI(OFF_DEGM);
    if (i < NN) degN[i] = 0;
    if (i < MM) degM[i] = 0;
}

__global__ void count_deg_kernel(const int* __restrict__ node_idx,
                                 const int* __restrict__ edge_idx) {
    int* degN = scrI(OFF_DEGN);
    int* degM = scrI(OFF_DEGM);
    int stride = gridDim.x * blockDim.x;
    for (int i = blockIdx.x * blockDim.x + threadIdx.x; i < NNZV; i += stride) {
        atomicAdd(&degN[node_idx[i]], 1);
        atomicAdd(&degM[edge_idx[i]], 1);
    }
}

constexpr int SC_ELEMS = 1024;
constexpr int NBLK_N = (NN + SC_ELEMS - 1) / SC_ELEMS;   // 49
constexpr int NBLK_M = (MM + SC_ELEMS - 1) / SC_ELEMS;   // 25
constexpr int NBLK_T = NBLK_N + NBLK_M;                  // 74

__global__ __launch_bounds__(256) void scanA_kernel() {
    int blk = blockIdx.x;
    const int* deg;
    int n, b;
    if (blk < NBLK_N) { deg = scrI(OFF_DEGN); n = NN; b = blk; }
    else              { deg = scrI(OFF_DEGM); n = MM; b = blk - NBLK_N; }
    int tid = threadIdx.x;
    int base = b * SC_ELEMS + tid * 4;
    int s = 0;
    #pragma unroll
    for (int j = 0; j < 4; j++) {
        int i = base + j;
        if (i < n) s += deg[i];
    }
    __shared__ int wsum[8];
    for (int d2 = 16; d2 > 0; d2 >>= 1) s += __shfl_down_sync(0xffffffffu, s, d2);
    if ((tid & 31) == 0) wsum[tid >> 5] = s;
    __syncthreads();
    if (tid < 8) {
        int v = wsum[tid];
        for (int d2 = 4; d2 > 0; d2 >>= 1) v += __shfl_down_sync(0xffu, v, d2);
        if (tid == 0) scrI(OFF_BS)[blk] = v;
    }
}

__global__ void scanB_kernel() {
    __shared__ int sh[128];
    int tid = threadIdx.x;
    const int* bs = scrI(OFF_BS);
    sh[tid] = (tid < NBLK_T) ? bs[tid] : 0;
    __syncthreads();
    for (int d = 1; d < 128; d <<= 1) {
        int v = (tid >= d) ? sh[tid - d] : 0;
        __syncthreads();
        sh[tid] += v;
        __syncthreads();
    }
    if (tid < NBLK_T) {
        int pre = (tid == 0) ? 0 : sh[tid - 1];
        if (tid >= NBLK_N) pre -= sh[NBLK_N - 1];
        scrI(OFF_BP)[tid] = pre;
    }
}

__global__ __launch_bounds__(256) void scanC_kernel() {
    int blk = blockIdx.x;
    const int* deg; int* off; int* cur; float* inv;
    int n, b;
    if (blk < NBLK_N) {
        deg = scrI(OFF_DEGN); off = scrI(OFF_OFFN); cur = scrI(OFF_CURN);
        inv = scrF(OFF_DINV); n = NN; b = blk;
    } else {
        deg = scrI(OFF_DEGM); off = scrI(OFF_OFFM); cur = scrI(OFF_CURM);
        inv = scrF(OFF_BINV); n = MM; b = blk - NBLK_N;
    }
    int tid = threadIdx.x;
    int base = b * SC_ELEMS + tid * 4;
    int d[4];
    int s = 0;
    #pragma unroll
    for (int j = 0; j < 4; j++) {
        int i = base + j;
        d[j] = (i < n) ? deg[i] : 0;
        s += d[j];
    }
    __shared__ int sh[256];
    sh[tid] = s;
    __syncthreads();
    for (int dd = 1; dd < 256; dd <<= 1) {
        int v = (tid >= dd) ? sh[tid - dd] : 0;
        __syncthreads();
        sh[tid] += v;
        __syncthreads();
    }
    int run = scrI(OFF_BP)[blk] + ((tid == 0) ? 0 : sh[tid - 1]);
    #pragma unroll
    for (int j = 0; j < 4; j++) {
        int i = base + j;
        if (i < n) {
            off[i] = run;
            cur[i] = run;
            inv[i] = (d[j] > 0) ? (1.0f / (float)d[j]) : 0.0f;
            run += d[j];
        }
    }
}

__global__ void fill_csr_kernel(const int* __restrict__ node_idx,
                                const int* __restrict__ edge_idx) {
    int* curN = scrI(OFF_CURN);
    int* curM = scrI(OFF_CURM);
    int* nodeEdges = scrI(OFF_NE);
    int* edgeNodes = scrI(OFF_EN);
    int stride = gridDim.x * blockDim.x;
    for (int i = blockIdx.x * blockDim.x + threadIdx.x; i < NNZV; i += stride) {
        int n = node_idx[i];
        int m = edge_idx[i];
        int p = atomicAdd(&curN[n], 1);
        nodeEdges[p] = m;
        int q = atomicAdd(&curM[m], 1);
        edgeNodes[q] = n;
    }
}

// ---------------------------------------------------------------------------
// Convert x (fp32) -> xh (fp16). NN*32 float4 granules.
// ---------------------------------------------------------------------------
__global__ __launch_bounds__(256) void conv_f2h_kernel(const float4* __restrict__ x) {
    uint2* xh = reinterpret_cast<uint2*>(g_scratch + OFF_XH);
    int stride = gridDim.x * blockDim.x;
    for (int i = blockIdx.x * blockDim.x + threadIdx.x; i < NN * 32; i += stride) {
        float4 v = __ldg(&x[i]);
        __half2 h01 = __floats2half2_rn(v.x, v.y);
        __half2 h23 = __floats2half2_rn(v.z, v.w);
        uint2 o;
        o.x = *reinterpret_cast<uint32_t*>(&h01);
        o.y = *reinterpret_cast<uint32_t*>(&h23);
        xh[i] = o;
    }
}

// ---------------------------------------------------------------------------
// Gather-reduce over fp16 sources (C = 128). Each of 32 lanes handles 4 cols.
// dst optionally fp32 (external or scratch) and/or fp16 (scratch).
// ---------------------------------------------------------------------------
template<bool HAS_BIAS, bool OUT_F, bool OUT_H>
__global__ void gather_h_kernel(size_t srcOff,
                                float* dstFext, size_t dstFOff,
                                size_t dstHOff,
                                size_t offOff, size_t degOff,
                                size_t lstOff, size_t invOff,
                                const float* __restrict__ bias,
                                int nrows)
{
    const uint2* __restrict__ src =
        reinterpret_cast<const uint2*>(g_scratch + srcOff);
    const int* __restrict__ off = scrI(offOff);
    const int* __restrict__ deg = scrI(degOff);
    const int* __restrict__ lst = scrI(lstOff);
    const float* __restrict__ inv = scrF(invOff);

    int row = blockIdx.x * blockDim.y + threadIdx.y;
    if (row >= nrows) return;
    int tx = threadIdx.x;   // 0..31
    int o = off[row];
    int d = deg[row];

    float a0 = 0.f, a1 = 0.f, a2 = 0.f, a3 = 0.f;
    int j = 0;
    for (; j + 4 <= d; j += 4) {
        int i0 = __ldg(&lst[o + j + 0]);
        int i1 = __ldg(&lst[o + j + 1]);
        int i2 = __ldg(&lst[o + j + 2]);
        int i3 = __ldg(&lst[o + j + 3]);
        uint2 v0 = __ldg(&src[(size_t)i0 * 32 + tx]);
        uint2 v1 = __ldg(&src[(size_t)i1 * 32 + tx]);
        uint2 v2 = __ldg(&src[(size_t)i2 * 32 + tx]);
        uint2 v3 = __ldg(&src[(size_t)i3 * 32 + tx]);
        float2 f;
        f = __half22float2(*reinterpret_cast<__half2*>(&v0.x)); a0 += f.x; a1 += f.y;
        f = __half22float2(*reinterpret_cast<__half2*>(&v0.y)); a2 += f.x; a3 += f.y;
        f = __half22float2(*reinterpret_cast<__half2*>(&v1.x)); a0 += f.x; a1 += f.y;
        f = __half22float2(*reinterpret_cast<__half2*>(&v1.y)); a2 += f.x; a3 += f.y;
        f = __half22float2(*reinterpret_cast<__half2*>(&v2.x)); a0 += f.x; a1 += f.y;
        f = __half22float2(*reinterpret_cast<__half2*>(&v2.y)); a2 += f.x; a3 += f.y;
        f = __half22float2(*reinterpret_cast<__half2*>(&v3.x)); a0 += f.x; a1 += f.y;
        f = __half22float2(*reinterpret_cast<__half2*>(&v3.y)); a2 += f.x; a3 += f.y;
    }
    for (; j < d; j++) {
        int i0 = __ldg(&lst[o + j]);
        uint2 v0 = __ldg(&src[(size_t)i0 * 32 + tx]);
        float2 f;
        f = __half22float2(*reinterpret_cast<__half2*>(&v0.x)); a0 += f.x; a1 += f.y;
        f = __half22float2(*reinterpret_cast<__half2*>(&v0.y)); a2 += f.x; a3 += f.y;
    }

    float s = inv[row];
    a0 *= s; a1 *= s; a2 *= s; a3 *= s;
    if (HAS_BIAS) {
        float4 b = __ldg(&reinterpret_cast<const float4*>(bias)[tx]);
        a0 += b.x; a1 += b.y; a2 += b.z; a3 += b.w;
    }
    if (OUT_F) {
        float4* dstF = dstFext
            ? reinterpret_cast<float4*>(dstFext)
            : reinterpret_cast<float4*>(g_scratch + dstFOff);
        dstF[(size_t)row * 32 + tx] = make_float4(a0, a1, a2, a3);
    }
    if (OUT_H) {
        uint2* dstH = reinterpret_cast<uint2*>(g_scratch + dstHOff);
        __half2 h01 = __floats2half2_rn(a0, a1);
        __half2 h23 = __floats2half2_rn(a2, a3);
        uint2 ov;
        ov.x = *reinterpret_cast<uint32_t*>(&h01);
        ov.y = *reinterpret_cast<uint32_t*>(&h23);
        dstH[(size_t)row * 32 + tx] = ov;
    }
}

// ---------------------------------------------------------------------------
// Double-buffered FFMA GEMM: C[M,N] = A[M,K] @ B[K,N].
// 128x128 block tile, BK=8, 8x8 per thread, 256 threads, 2-stage smem
// pipeline with register prefetch (one __syncthreads per K-step).
// Optional bias + ELU; C stored fp32 or fp16.
// ---------------------------------------------------------------------------
template<bool C_HALF, bool HAS_BIAS, bool HAS_ELU>
__global__ __launch_bounds__(256) void gemm_db_kernel(
    size_t aOff, const float* __restrict__ B,
    size_t cOff, const float* __restrict__ bias,
    int Mrows, int K, int Ncols)
{
    const float* __restrict__ A = scrF(aOff);

    __shared__ float As[2][8][132];   // transposed [k][m], padded
    __shared__ float Bs[2][8][128];

    int tid = threadIdx.x;
    int tx = tid & 15;
    int ty = tid >> 4;
    int rowBase = blockIdx.y * 128;
    int colBase = blockIdx.x * 128;

    int aRow = tid >> 1;           // 0..127
    int aK4  = tid & 1;            // 0..1
    int bK   = tid >> 5;           // 0..7
    int bC4  = tid & 31;           // 0..31

    float acc[8][8] = {};
    float ra[4], rb[4];

    int gmA = rowBase + aRow;
    const float* aBase = &A[(size_t)gmA * K + aK4 * 4];
    const float* bBase = &B[(size_t)bK * Ncols + colBase + bC4 * 4];
    bool aValid = (gmA < Mrows);

    // preload tile 0
    {
        float4 va = make_float4(0.f, 0.f, 0.f, 0.f);
        if (aValid) va = *(const float4*)aBase;
        ra[0] = va.x; ra[1] = va.y; ra[2] = va.z; ra[3] = va.w;
        float4 vb = *(const float4*)bBase;
        rb[0] = vb.x; rb[1] = vb.y; rb[2] = vb.z; rb[3] = vb.w;
    }
    As[0][aK4 * 4 + 0][aRow] = ra[0];
    As[0][aK4 * 4 + 1][aRow] = ra[1];
    As[0][aK4 * 4 + 2][aRow] = ra[2];
    As[0][aK4 * 4 + 3][aRow] = ra[3];
    *(float4*)&Bs[0][bK][bC4 * 4] = make_float4(rb[0], rb[1], rb[2], rb[3]);
    __syncthreads();

    int nIter = K >> 3;
    for (int it = 0; it < nIter; it++) {
        int buf = it & 1;
        bool more = (it + 1 < nIter);
        if (more) {
            int k0 = (it + 1) * 8;
            float4 va = make_float4(0.f, 0.f, 0.f, 0.f);
            if (aValid) va = *(const float4*)(aBase + k0);
            ra[0] = va.x; ra[1] = va.y; ra[2] = va.z; ra[3] = va.w;
            float4 vb = *(const float4*)(bBase + (size_t)k0 * Ncols);
            rb[0] = vb.x; rb[1] = vb.y; rb[2] = vb.z; rb[3] = vb.w;
        }

        #pragma unroll
        for (int k = 0; k < 8; k++) {
            float4 a0 = *(const float4*)&As[buf][k][ty * 8];
            float4 a1 = *(const float4*)&As[buf][k][ty * 8 + 4];
            float4 b0 = *(const float4*)&Bs[buf][k][tx * 8];
            float4 b1 = *(const float4*)&Bs[buf][k][tx * 8 + 4];
            float a[8] = {a0.x, a0.y, a0.z, a0.w, a1.x, a1.y, a1.z, a1.w};
            float b[8] = {b0.x, b0.y, b0.z, b0.w, b1.x, b1.y, b1.z, b1.w};
            #pragma unroll
            for (int i = 0; i < 8; i++)
                #pragma unroll
                for (int j = 0; j < 8; j++)
                    acc[i][j] += a[i] * b[j];
        }

        if (more) {
            int nb = buf ^ 1;
            As[nb][aK4 * 4 + 0][aRow] = ra[0];
            As[nb][aK4 * 4 + 1][aRow] = ra[1];
            As[nb][aK4 * 4 + 2][aRow] = ra[2];
            As[nb][aK4 * 4 + 3][aRow] = ra[3];
            *(float4*)&Bs[nb][bK][bC4 * 4] = make_float4(rb[0], rb[1], rb[2], rb[3]);
        }
        __syncthreads();
    }

    float bb[8];
    if (HAS_BIAS) {
        float4 c0 = __ldg(&((const float4*)&bias[colBase])[tx * 2]);
        float4 c1 = __ldg(&((const float4*)&bias[colBase])[tx * 2 + 1]);
        bb[0]=c0.x; bb[1]=c0.y; bb[2]=c0.z; bb[3]=c0.w;
        bb[4]=c1.x; bb[5]=c1.y; bb[6]=c1.z; bb[7]=c1.w;
    }

    #pragma unroll
    for (int i = 0; i < 8; i++) {
        int gm = rowBase + ty * 8 + i;
        if (gm >= Mrows) continue;
        float r[8];
        #pragma unroll
        for (int j = 0; j < 8; j++) {
            float v = acc[i][j];
            if (HAS_BIAS) v += bb[j];
            if (HAS_ELU)  v = (v > 0.f) ? v : expm1f(v);
            r[j] = v;
        }
        if (C_HALF) {
            __half* Ch = scrH(cOff);
            __half2 h0 = __floats2half2_rn(r[0], r[1]);
            __half2 h1 = __floats2half2_rn(r[2], r[3]);
            __half2 h2 = __floats2half2_rn(r[4], r[5]);
            __half2 h3 = __floats2half2_rn(r[6], r[7]);
            uint4 ov;
            ov.x = *reinterpret_cast<uint32_t*>(&h0);
            ov.y = *reinterpret_cast<uint32_t*>(&h1);
            ov.z = *reinterpret_cast<uint32_t*>(&h2);
            ov.w = *reinterpret_cast<uint32_t*>(&h3);
            *reinterpret_cast<uint4*>(&Ch[(size_t)gm * Ncols + colBase + tx * 8]) = ov;
        } else {
            float* C = scrF(cOff);
            float* cp = &C[(size_t)gm * Ncols + colBase + tx * 8];
            *(float4*)cp       = make_float4(r[0], r[1], r[2], r[3]);
            *(float4*)(cp + 4) = make_float4(r[4], r[5], r[6], r[7]);
        }
    }
}

// ---------------------------------------------------------------------------
// Launch: kernel launches ONLY.
// ---------------------------------------------------------------------------
extern "C" void kernel_launch(void* const* d_in, const int* in_sizes, int n_in,
                              void* d_out, int out_size)
{
    const float* x        = (const float*)d_in[0];
    const float* W1       = (const float*)d_in[1];
    const float* b1       = (const float*)d_in[2];
    const float* W2       = (const float*)d_in[3];
    const float* b2       = (const float*)d_in[4];
    const int*   node_idx = (const int*)d_in[5];
    const int*   edge_idx = (const int*)d_in[6];

    float* out   = (float*)d_out;
    float* e_out = out + (size_t)NN * F_OUT;

    // ---- CSR build + x conversion ----
    zero_deg_kernel<<<(NN + 255) / 256, 256>>>();
    conv_f2h_kernel<<<1024, 256>>>((const float4*)x);
    count_deg_kernel<<<2048, 256>>>(node_idx, edge_idx);
    scanA_kernel<<<NBLK_T, 256>>>();
    scanB_kernel<<<1, 128>>>();
    scanC_kernel<<<NBLK_T, 256>>>();
    fill_csr_kernel<<<2048, 256>>>(node_idx, edge_idx);

    dim3 gblk(32, 8);   // 256 threads, 8 rows/block

    // ---- Layer 1 (GEMM commuted past both segment-sums) ----
    // t1h[m] = Binv[m] * sum_{n in edge m} xh[n]         (fp16 out)
    gather_h_kernel<false, false, true><<<(MM + 7) / 8, gblk>>>(
        OFF_XH, nullptr, 0, OFF_T1H,
        OFF_OFFM, OFF_DEGM, OFF_EN, OFF_BINV, nullptr, MM);
    // t2[n] = Dinv[n] * sum_{m in node n} t1h[m]         (fp32 out)
    gather_h_kernel<false, true, false><<<(NN + 7) / 8, gblk>>>(
        OFF_T1H, nullptr, OFF_T2, 0,
        OFF_OFFN, OFF_DEGN, OFF_NE, OFF_DINV, nullptr, NN);
    // h = elu(t2 @ W1 + b1)
    {
        dim3 grid(HIDC / 128, (NN + 127) / 128);
        gemm_db_kernel<false, true, true><<<grid, 256>>>(
            OFF_T2, W1, OFF_H, b1, NN, F_IN, HIDC);
    }

    // ---- Layer 2 ----
    // x2h = h @ W2   (fp16 out)
    {
        dim3 grid(F_OUT / 128, (NN + 127) / 128);
        gemm_db_kernel<true, false, false><<<grid, 256>>>(
            OFF_H, W2, OFF_X2H, nullptr, NN, HIDC, F_OUT);
    }
    // e_out[m] (fp32, returned) + eh[m] (fp16 copy) = Binv[m]*sum x2h[n]
    gather_h_kernel<false, true, true><<<(MM + 7) / 8, gblk>>>(
        OFF_X2H, e_out, 0, OFF_EH,
        OFF_OFFM, OFF_DEGM, OFF_EN, OFF_BINV, nullptr, MM);
    // out[n] = Dinv[n] * sum_{m in node n} eh[m] + b2
    gather_h_kernel<true, true, false><<<(NN + 7) / 8, gblk>>>(
        OFF_EH, out, 0, 0,
        OFF_OFFN, OFF_DEGN, OFF_NE, OFF_DINV, b2, NN);
}

// round 7
// speedup vs baseline: 1.6140x; 1.0643x over previous
#include <cuda_runtime.h>
#include <cuda_fp16.h>
#include <cstdint>

#define NN   50000
#define MM   25000
#define NNZV 800000
#define F_IN 128
#define HIDC 256
#define F_OUT 128

// ---------------------------------------------------------------------------
// Scratch (single __device__ array; resolved in device code only)
// ---------------------------------------------------------------------------
constexpr size_t SZ_XH   = (size_t)NN * F_IN * 2;
constexpr size_t SZ_T1H  = (size_t)MM * F_IN * 2;
constexpr size_t SZ_T2   = (size_t)NN * F_IN * 4;
constexpr size_t SZ_H    = (size_t)NN * HIDC * 4;
constexpr size_t SZ_X2H  = (size_t)NN * F_OUT * 2;
constexpr size_t SZ_EH   = (size_t)MM * F_OUT * 2;
constexpr size_t SZ_DEGN = (size_t)NN * 4;
constexpr size_t SZ_DEGM = (size_t)MM * 4;
constexpr size_t SZ_OFFN = (size_t)NN * 4;
constexpr size_t SZ_OFFM = (size_t)MM * 4;
constexpr size_t SZ_CURN = (size_t)NN * 4;
constexpr size_t SZ_CURM = (size_t)MM * 4;
constexpr size_t SZ_DINV = (size_t)NN * 4;
constexpr size_t SZ_BINV = (size_t)MM * 4;
constexpr size_t SZ_NE   = (size_t)NNZV * 4;
constexpr size_t SZ_EN   = (size_t)NNZV * 4;
constexpr size_t SZ_BS   = 256 * 4;
constexpr size_t SZ_BP   = 256 * 4;

constexpr size_t OFF_XH   = 0;
constexpr size_t OFF_T1H  = OFF_XH + SZ_XH;
constexpr size_t OFF_T2   = OFF_T1H + SZ_T1H;
constexpr size_t OFF_H    = OFF_T2 + SZ_T2;
constexpr size_t OFF_X2H  = OFF_H + SZ_H;
constexpr size_t OFF_EH   = OFF_X2H + SZ_X2H;
constexpr size_t OFF_DEGN = OFF_EH + SZ_EH;
constexpr size_t OFF_DEGM = OFF_DEGN + SZ_DEGN;
constexpr size_t OFF_OFFN = OFF_DEGM + SZ_DEGM;
constexpr size_t OFF_OFFM = OFF_OFFN + SZ_OFFN;
constexpr size_t OFF_CURN = OFF_OFFM + SZ_OFFM;
constexpr size_t OFF_CURM = OFF_CURN + SZ_CURN;
constexpr size_t OFF_DINV = OFF_CURM + SZ_CURM;
constexpr size_t OFF_BINV = OFF_DINV + SZ_DINV;
constexpr size_t OFF_NE   = OFF_BINV + SZ_BINV;
constexpr size_t OFF_EN   = OFF_NE + SZ_NE;
constexpr size_t OFF_BS   = OFF_EN + SZ_EN;
constexpr size_t OFF_BP   = OFF_BS + SZ_BS;
constexpr size_t SCRATCH_TOTAL = OFF_BP + SZ_BP;

__device__ __align__(256) unsigned char g_scratch[SCRATCH_TOTAL];

__device__ __forceinline__ float* scrF(size_t off) {
    return reinterpret_cast<float*>(g_scratch + off);
}
__device__ __forceinline__ int* scrI(size_t off) {
    return reinterpret_cast<int*>(g_scratch + off);
}
__device__ __forceinline__ __half* scrH(size_t off) {
    return reinterpret_cast<__half*>(g_scratch + off);
}

// ---------------------------------------------------------------------------
// Packed f32x2 helpers (Blackwell FFMA2 path; PTX-only, ptxas won't emit it)
// ---------------------------------------------------------------------------
__device__ __forceinline__ unsigned long long pack2(float lo, float hi) {
    unsigned long long r;
    asm("mov.b64 %0, {%1, %2};" : "=l"(r) : "f"(lo), "f"(hi));
    return r;
}
__device__ __forceinline__ void fma2(unsigned long long& d,
                                     unsigned long long a,
                                     unsigned long long b) {
    asm("fma.rn.f32x2 %0, %1, %2, %0;" : "+l"(d) : "l"(a), "l"(b));
}
__device__ __forceinline__ void unpack2(float& lo, float& hi,
                                        unsigned long long v) {
    asm("mov.b64 {%0, %1}, %2;" : "=f"(lo), "=f"(hi) : "l"(v));
}

// ---------------------------------------------------------------------------
// CSR build
// ---------------------------------------------------------------------------
__global__ void zero_deg_kernel() {
    int i = blockIdx.x * blockDim.x + threadIdx.x;
    int* degN = scrI(OFF_DEGN);
    int* degM = scrI(OFF_DEGM);
    if (i < NN) degN[i] = 0;
    if (i < MM) degM[i] = 0;
}

__global__ void count_deg_kernel(const int* __restrict__ node_idx,
                                 const int* __restrict__ edge_idx) {
    int* degN = scrI(OFF_DEGN);
    int* degM = scrI(OFF_DEGM);
    int stride = gridDim.x * blockDim.x;
    for (int i = blockIdx.x * blockDim.x + threadIdx.x; i < NNZV; i += stride) {
        atomicAdd(&degN[node_idx[i]], 1);
        atomicAdd(&degM[edge_idx[i]], 1);
    }
}

constexpr int SC_ELEMS = 1024;
constexpr int NBLK_N = (NN + SC_ELEMS - 1) / SC_ELEMS;   // 49
constexpr int NBLK_M = (MM + SC_ELEMS - 1) / SC_ELEMS;   // 25
constexpr int NBLK_T = NBLK_N + NBLK_M;                  // 74

__global__ __launch_bounds__(256) void scanA_kernel() {
    int blk = blockIdx.x;
    const int* deg;
    int n, b;
    if (blk < NBLK_N) { deg = scrI(OFF_DEGN); n = NN; b = blk; }
    else              { deg = scrI(OFF_DEGM); n = MM; b = blk - NBLK_N; }
    int tid = threadIdx.x;
    int base = b * SC_ELEMS + tid * 4;
    int s = 0;
    #pragma unroll
    for (int j = 0; j < 4; j++) {
        int i = base + j;
        if (i < n) s += deg[i];
    }
    __shared__ int wsum[8];
    for (int d2 = 16; d2 > 0; d2 >>= 1) s += __shfl_down_sync(0xffffffffu, s, d2);
    if ((tid & 31) == 0) wsum[tid >> 5] = s;
    __syncthreads();
    if (tid < 8) {
        int v = wsum[tid];
        for (int d2 = 4; d2 > 0; d2 >>= 1) v += __shfl_down_sync(0xffu, v, d2);
        if (tid == 0) scrI(OFF_BS)[blk] = v;
    }
}

__global__ void scanB_kernel() {
    __shared__ int sh[128];
    int tid = threadIdx.x;
    const int* bs = scrI(OFF_BS);
    sh[tid] = (tid < NBLK_T) ? bs[tid] : 0;
    __syncthreads();
    for (int d = 1; d < 128; d <<= 1) {
        int v = (tid >= d) ? sh[tid - d] : 0;
        __syncthreads();
        sh[tid] += v;
        __syncthreads();
    }
    if (tid < NBLK_T) {
        int pre = (tid == 0) ? 0 : sh[tid - 1];
        if (tid >= NBLK_N) pre -= sh[NBLK_N - 1];
        scrI(OFF_BP)[tid] = pre;
    }
}

__global__ __launch_bounds__(256) void scanC_kernel() {
    int blk = blockIdx.x;
    const int* deg; int* off; int* cur; float* inv;
    int n, b;
    if (blk < NBLK_N) {
        deg = scrI(OFF_DEGN); off = scrI(OFF_OFFN); cur = scrI(OFF_CURN);
        inv = scrF(OFF_DINV); n = NN; b = blk;
    } else {
        deg = scrI(OFF_DEGM); off = scrI(OFF_OFFM); cur = scrI(OFF_CURM);
        inv = scrF(OFF_BINV); n = MM; b = blk - NBLK_N;
    }
    int tid = threadIdx.x;
    int base = b * SC_ELEMS + tid * 4;
    int d[4];
    int s = 0;
    #pragma unroll
    for (int j = 0; j < 4; j++) {
        int i = base + j;
        d[j] = (i < n) ? deg[i] : 0;
        s += d[j];
    }
    __shared__ int sh[256];
    sh[tid] = s;
    __syncthreads();
    for (int dd = 1; dd < 256; dd <<= 1) {
        int v = (tid >= dd) ? sh[tid - dd] : 0;
        __syncthreads();
        sh[tid] += v;
        __syncthreads();
    }
    int run = scrI(OFF_BP)[blk] + ((tid == 0) ? 0 : sh[tid - 1]);
    #pragma unroll
    for (int j = 0; j < 4; j++) {
        int i = base + j;
        if (i < n) {
            off[i] = run;
            cur[i] = run;
            inv[i] = (d[j] > 0) ? (1.0f / (float)d[j]) : 0.0f;
            run += d[j];
        }
    }
}

__global__ void fill_csr_kernel(const int* __restrict__ node_idx,
                                const int* __restrict__ edge_idx) {
    int* curN = scrI(OFF_CURN);
    int* curM = scrI(OFF_CURM);
    int* nodeEdges = scrI(OFF_NE);
    int* edgeNodes = scrI(OFF_EN);
    int stride = gridDim.x * blockDim.x;
    for (int i = blockIdx.x * blockDim.x + threadIdx.x; i < NNZV; i += stride) {
        int n = node_idx[i];
        int m = edge_idx[i];
        int p = atomicAdd(&curN[n], 1);
        nodeEdges[p] = m;
        int q = atomicAdd(&curM[m], 1);
        edgeNodes[q] = n;
    }
}

// ---------------------------------------------------------------------------
// Convert x (fp32) -> xh (fp16)
// ---------------------------------------------------------------------------
__global__ __launch_bounds__(256) void conv_f2h_kernel(const float4* __restrict__ x) {
    uint2* xh = reinterpret_cast<uint2*>(g_scratch + OFF_XH);
    int stride = gridDim.x * blockDim.x;
    for (int i = blockIdx.x * blockDim.x + threadIdx.x; i < NN * 32; i += stride) {
        float4 v = __ldg(&x[i]);
        __half2 h01 = __floats2half2_rn(v.x, v.y);
        __half2 h23 = __floats2half2_rn(v.z, v.w);
        uint2 o;
        o.x = *reinterpret_cast<uint32_t*>(&h01);
        o.y = *reinterpret_cast<uint32_t*>(&h23);
        xh[i] = o;
    }
}

// ---------------------------------------------------------------------------
// Gather-reduce over fp16 sources (C = 128). 16 lanes per row, uint4 loads
// (LDG.128). blockDim = (16, 16): two rows per warp, half warps vs before.
// ---------------------------------------------------------------------------
template<bool HAS_BIAS, bool OUT_F, bool OUT_H>
__global__ void gather_h_kernel(size_t srcOff,
                                float* dstFext, size_t dstFOff,
                                size_t dstHOff,
                                size_t offOff, size_t degOff,
                                size_t lstOff, size_t invOff,
                                const float* __restrict__ bias,
                                int nrows)
{
    const uint4* __restrict__ src =
        reinterpret_cast<const uint4*>(g_scratch + srcOff);   // row = 16 uint4
    const int* __restrict__ off = scrI(offOff);
    const int* __restrict__ deg = scrI(degOff);
    const int* __restrict__ lst = scrI(lstOff);
    const float* __restrict__ inv = scrF(invOff);

    int row = blockIdx.x * blockDim.y + threadIdx.y;
    if (row >= nrows) return;
    int tx = threadIdx.x;   // 0..15
    int o = off[row];
    int d = deg[row];

    float a0 = 0.f, a1 = 0.f, a2 = 0.f, a3 = 0.f;
    float a4 = 0.f, a5 = 0.f, a6 = 0.f, a7 = 0.f;

    int j = 0;
    for (; j + 4 <= d; j += 4) {
        int i0 = __ldg(&lst[o + j + 0]);
        int i1 = __ldg(&lst[o + j + 1]);
        int i2 = __ldg(&lst[o + j + 2]);
        int i3 = __ldg(&lst[o + j + 3]);
        uint4 v0 = __ldg(&src[(size_t)i0 * 16 + tx]);
        uint4 v1 = __ldg(&src[(size_t)i1 * 16 + tx]);
        uint4 v2 = __ldg(&src[(size_t)i2 * 16 + tx]);
        uint4 v3 = __ldg(&src[(size_t)i3 * 16 + tx]);
        float2 f;
        f = __half22float2(*reinterpret_cast<__half2*>(&v0.x)); a0 += f.x; a1 += f.y;
        f = __half22float2(*reinterpret_cast<__half2*>(&v0.y)); a2 += f.x; a3 += f.y;
        f = __half22float2(*reinterpret_cast<__half2*>(&v0.z)); a4 += f.x; a5 += f.y;
        f = __half22float2(*reinterpret_cast<__half2*>(&v0.w)); a6 += f.x; a7 += f.y;
        f = __half22float2(*reinterpret_cast<__half2*>(&v1.x)); a0 += f.x; a1 += f.y;
        f = __half22float2(*reinterpret_cast<__half2*>(&v1.y)); a2 += f.x; a3 += f.y;
        f = __half22float2(*reinterpret_cast<__half2*>(&v1.z)); a4 += f.x; a5 += f.y;
        f = __half22float2(*reinterpret_cast<__half2*>(&v1.w)); a6 += f.x; a7 += f.y;
        f = __half22float2(*reinterpret_cast<__half2*>(&v2.x)); a0 += f.x; a1 += f.y;
        f = __half22float2(*reinterpret_cast<__half2*>(&v2.y)); a2 += f.x; a3 += f.y;
        f = __half22float2(*reinterpret_cast<__half2*>(&v2.z)); a4 += f.x; a5 += f.y;
        f = __half22float2(*reinterpret_cast<__half2*>(&v2.w)); a6 += f.x; a7 += f.y;
        f = __half22float2(*reinterpret_cast<__half2*>(&v3.x)); a0 += f.x; a1 += f.y;
        f = __half22float2(*reinterpret_cast<__half2*>(&v3.y)); a2 += f.x; a3 += f.y;
        f = __half22float2(*reinterpret_cast<__half2*>(&v3.z)); a4 += f.x; a5 += f.y;
        f = __half22float2(*reinterpret_cast<__half2*>(&v3.w)); a6 += f.x; a7 += f.y;
    }
    for (; j < d; j++) {
        int i0 = __ldg(&lst[o + j]);
        uint4 v0 = __ldg(&src[(size_t)i0 * 16 + tx]);
        float2 f;
        f = __half22float2(*reinterpret_cast<__half2*>(&v0.x)); a0 += f.x; a1 += f.y;
        f = __half22float2(*reinterpret_cast<__half2*>(&v0.y)); a2 += f.x; a3 += f.y;
        f = __half22float2(*reinterpret_cast<__half2*>(&v0.z)); a4 += f.x; a5 += f.y;
        f = __half22float2(*reinterpret_cast<__half2*>(&v0.w)); a6 += f.x; a7 += f.y;
    }

    float s = inv[row];
    a0 *= s; a1 *= s; a2 *= s; a3 *= s;
    a4 *= s; a5 *= s; a6 *= s; a7 *= s;
    if (HAS_BIAS) {
        const float4* b4 = reinterpret_cast<const float4*>(bias);
        float4 b0 = __ldg(&b4[tx * 2]);
        float4 b1 = __ldg(&b4[tx * 2 + 1]);
        a0 += b0.x; a1 += b0.y; a2 += b0.z; a3 += b0.w;
        a4 += b1.x; a5 += b1.y; a6 += b1.z; a7 += b1.w;
    }
    if (OUT_F) {
        float4* dstF = dstFext
            ? reinterpret_cast<float4*>(dstFext)
            : reinterpret_cast<float4*>(g_scratch + dstFOff);
        dstF[(size_t)row * 32 + tx * 2]     = make_float4(a0, a1, a2, a3);
        dstF[(size_t)row * 32 + tx * 2 + 1] = make_float4(a4, a5, a6, a7);
    }
    if (OUT_H) {
        uint4* dstH = reinterpret_cast<uint4*>(g_scratch + dstHOff);
        __half2 h0 = __floats2half2_rn(a0, a1);
        __half2 h1 = __floats2half2_rn(a2, a3);
        __half2 h2 = __floats2half2_rn(a4, a5);
        __half2 h3 = __floats2half2_rn(a6, a7);
        uint4 ov;
        ov.x = *reinterpret_cast<uint32_t*>(&h0);
        ov.y = *reinterpret_cast<uint32_t*>(&h1);
        ov.z = *reinterpret_cast<uint32_t*>(&h2);
        ov.w = *reinterpret_cast<uint32_t*>(&h3);
        dstH[(size_t)row * 16 + tx] = ov;
    }
}

// ---------------------------------------------------------------------------
// Double-buffered GEMM with packed f32x2 FMA: C[M,N] = A[M,K] @ B[K,N].
// 128x128 block tile, BK=8, 8x8 per thread (accumulated as 8x4 f32x2 pairs),
// 256 threads, 2-stage smem pipeline.
// ---------------------------------------------------------------------------
template<bool C_HALF, bool HAS_BIAS, bool HAS_ELU>
__global__ __launch_bounds__(256) void gemm_db_kernel(
    size_t aOff, const float* __restrict__ B,
    size_t cOff, const float* __restrict__ bias,
    int Mrows, int K, int Ncols)
{
    const float* __restrict__ A = scrF(aOff);

    __shared__ float As[2][8][132];   // transposed [k][m], padded
    __shared__ float Bs[2][8][128];

    int tid = threadIdx.x;
    int tx = tid & 15;
    int ty = tid >> 4;
    int rowBase = blockIdx.y * 128;
    int colBase = blockIdx.x * 128;

    int aRow = tid >> 1;           // 0..127
    int aK4  = tid & 1;            // 0..1
    int bK   = tid >> 5;           // 0..7
    int bC4  = tid & 31;           // 0..31

    unsigned long long acc[8][4];  // [i][j2] packed f32x2 pairs over j
    #pragma unroll
    for (int i = 0; i < 8; i++)
        #pragma unroll
        for (int j2 = 0; j2 < 4; j2++)
            acc[i][j2] = 0ull;

    float ra[4], rb[4];
    int gmA = rowBase + aRow;
    const float* aBase = &A[(size_t)gmA * K + aK4 * 4];
    const float* bBase = &B[(size_t)bK * Ncols + colBase + bC4 * 4];
    bool aValid = (gmA < Mrows);

    {
        float4 va = make_float4(0.f, 0.f, 0.f, 0.f);
        if (aValid) va = *(const float4*)aBase;
        ra[0] = va.x; ra[1] = va.y; ra[2] = va.z; ra[3] = va.w;
        float4 vb = *(const float4*)bBase;
        rb[0] = vb.x; rb[1] = vb.y; rb[2] = vb.z; rb[3] = vb.w;
    }
    As[0][aK4 * 4 + 0][aRow] = ra[0];
    As[0][aK4 * 4 + 1][aRow] = ra[1];
    As[0][aK4 * 4 + 2][aRow] = ra[2];
    As[0][aK4 * 4 + 3][aRow] = ra[3];
    *(float4*)&Bs[0][bK][bC4 * 4] = make_float4(rb[0], rb[1], rb[2], rb[3]);
    __syncthreads();

    int nIter = K >> 3;
    for (int it = 0; it < nIter; it++) {
        int buf = it & 1;
        bool more = (it + 1 < nIter);
        if (more) {
            int k0 = (it + 1) * 8;
            float4 va = make_float4(0.f, 0.f, 0.f, 0.f);
            if (aValid) va = *(const float4*)(aBase + k0);
            ra[0] = va.x; ra[1] = va.y; ra[2] = va.z; ra[3] = va.w;
            float4 vb = *(const float4*)(bBase + (size_t)k0 * Ncols);
            rb[0] = vb.x; rb[1] = vb.y; rb[2] = vb.z; rb[3] = vb.w;
        }

        #pragma unroll
        for (int k = 0; k < 8; k++) {
            float4 a0 = *(const float4*)&As[buf][k][ty * 8];
            float4 a1 = *(const float4*)&As[buf][k][ty * 8 + 4];
            float4 b0 = *(const float4*)&Bs[buf][k][tx * 8];
            float4 b1 = *(const float4*)&Bs[buf][k][tx * 8 + 4];
            // b pairs (adjacent j), a duplicated per i
            unsigned long long bd[4];
            bd[0] = pack2(b0.x, b0.y);
            bd[1] = pack2(b0.z, b0.w);
            bd[2] = pack2(b1.x, b1.y);
            bd[3] = pack2(b1.z, b1.w);
            float av[8] = {a0.x, a0.y, a0.z, a0.w, a1.x, a1.y, a1.z, a1.w};
            #pragma unroll
            for (int i = 0; i < 8; i++) {
                unsigned long long ad = pack2(av[i], av[i]);
                #pragma unroll
                for (int j2 = 0; j2 < 4; j2++)
                    fma2(acc[i][j2], ad, bd[j2]);
            }
        }

        if (more) {
            int nb = buf ^ 1;
            As[nb][aK4 * 4 + 0][aRow] = ra[0];
            As[nb][aK4 * 4 + 1][aRow] = ra[1];
            As[nb][aK4 * 4 + 2][aRow] = ra[2];
            As[nb][aK4 * 4 + 3][aRow] = ra[3];
            *(float4*)&Bs[nb][bK][bC4 * 4] = make_float4(rb[0], rb[1], rb[2], rb[3]);
        }
        __syncthreads();
    }

    float bb[8];
    if (HAS_BIAS) {
        float4 c0 = __ldg(&((const float4*)&bias[colBase])[tx * 2]);
        float4 c1 = __ldg(&((const float4*)&bias[colBase])[tx * 2 + 1]);
        bb[0]=c0.x; bb[1]=c0.y; bb[2]=c0.z; bb[3]=c0.w;
        bb[4]=c1.x; bb[5]=c1.y; bb[6]=c1.z; bb[7]=c1.w;
    }

    #pragma unroll
    for (int i = 0; i < 8; i++) {
        int gm = rowBase + ty * 8 + i;
        if (gm >= Mrows) continue;
        float r[8];
        #pragma unroll
        for (int j2 = 0; j2 < 4; j2++)
            unpack2(r[2 * j2], r[2 * j2 + 1], acc[i][j2]);
        #pragma unroll
        for (int j = 0; j < 8; j++) {
            float v = r[j];
            if (HAS_BIAS) v += bb[j];
            if (HAS_ELU)  v = (v > 0.f) ? v : expm1f(v);
            r[j] = v;
        }
        if (C_HALF) {
            __half* Ch = scrH(cOff);
            __half2 h0 = __floats2half2_rn(r[0], r[1]);
            __half2 h1 = __floats2half2_rn(r[2], r[3]);
            __half2 h2 = __floats2half2_rn(r[4], r[5]);
            __half2 h3 = __floats2half2_rn(r[6], r[7]);
            uint4 ov;
            ov.x = *reinterpret_cast<uint32_t*>(&h0);
            ov.y = *reinterpret_cast<uint32_t*>(&h1);
            ov.z = *reinterpret_cast<uint32_t*>(&h2);
            ov.w = *reinterpret_cast<uint32_t*>(&h3);
            *reinterpret_cast<uint4*>(&Ch[(size_t)gm * Ncols + colBase + tx * 8]) = ov;
        } else {
            float* C = scrF(cOff);
            float* cp = &C[(size_t)gm * Ncols + colBase + tx * 8];
            *(float4*)cp       = make_float4(r[0], r[1], r[2], r[3]);
            *(float4*)(cp + 4) = make_float4(r[4], r[5], r[6], r[7]);
        }
    }
}

// ---------------------------------------------------------------------------
// Launch: kernel launches ONLY.
// ---------------------------------------------------------------------------
extern "C" void kernel_launch(void* const* d_in, const int* in_sizes, int n_in,
                              void* d_out, int out_size)
{
    const float* x        = (const float*)d_in[0];
    const float* W1       = (const float*)d_in[1];
    const float* b1       = (const float*)d_in[2];
    const float* W2       = (const float*)d_in[3];
    const float* b2       = (const float*)d_in[4];
    const int*   node_idx = (const int*)d_in[5];
    const int*   edge_idx = (const int*)d_in[6];

    float* out   = (float*)d_out;
    float* e_out = out + (size_t)NN * F_OUT;

    // ---- CSR build + x conversion ----
    zero_deg_kernel<<<(NN + 255) / 256, 256>>>();
    conv_f2h_kernel<<<1024, 256>>>((const float4*)x);
    count_deg_kernel<<<2048, 256>>>(node_idx, edge_idx);
    scanA_kernel<<<NBLK_T, 256>>>();
    scanB_kernel<<<1, 128>>>();
    scanC_kernel<<<NBLK_T, 256>>>();
    fill_csr_kernel<<<2048, 256>>>(node_idx, edge_idx);

    dim3 gblk(16, 16);   // 256 threads, 16 rows/block, 2 rows/warp

    // ---- Layer 1 (GEMM commuted past both segment-sums) ----
    gather_h_kernel<false, false, true><<<(MM + 15) / 16, gblk>>>(
        OFF_XH, nullptr, 0, OFF_T1H,
        OFF_OFFM, OFF_DEGM, OFF_EN, OFF_BINV, nullptr, MM);
    gather_h_kernel<false, true, false><<<(NN + 15) / 16, gblk>>>(
        OFF_T1H, nullptr, OFF_T2, 0,
        OFF_OFFN, OFF_DEGN, OFF_NE, OFF_DINV, nullptr, NN);
    // h = elu(t2 @ W1 + b1)
    {
        dim3 grid(HIDC / 128, (NN + 127) / 128);
        gemm_db_kernel<false, true, true><<<grid, 256>>>(
            OFF_T2, W1, OFF_H, b1, NN, F_IN, HIDC);
    }

    // ---- Layer 2 ----
    // x2h = h @ W2 (fp16 out)
    {
        dim3 grid(F_OUT / 128, (NN + 127) / 128);
        gemm_db_kernel<true, false, false><<<grid, 256>>>(
            OFF_H, W2, OFF_X2H, nullptr, NN, HIDC, F_OUT);
    }
    // e_out[m] (fp32, returned) + eh[m] (fp16 copy)
    gather_h_kernel<false, true, true><<<(MM + 15) / 16, gblk>>>(
        OFF_X2H, e_out, 0, OFF_EH,
        OFF_OFFM, OFF_DEGM, OFF_EN, OFF_BINV, nullptr, MM);
    // out[n] = Dinv[n] * sum eh[m] + b2
    gather_h_kernel<true, true, false><<<(NN + 15) / 16, gblk>>>(
        OFF_EH, out, 0, 0,
        OFF_OFFN, OFF_DEGN, OFF_NE, OFF_DINV, b2, NN);
}

// round 9
// speedup vs baseline: 2.6278x; 1.6281x over previous
#include <cuda_runtime.h>
#include <cuda_fp16.h>
#include <cstdint>

#define NN   50000
#define MM   25000
#define NNZV 800000
#define F_IN 128
#define HIDC 256
#define F_OUT 128

// ---------------------------------------------------------------------------
// Scratch (fp16 activation chain end-to-end)
// ---------------------------------------------------------------------------
constexpr size_t SZ_XH   = (size_t)NN * F_IN * 2;
constexpr size_t SZ_T1H  = (size_t)MM * F_IN * 2;
constexpr size_t SZ_T2H  = (size_t)NN * F_IN * 2;
constexpr size_t SZ_HH   = (size_t)NN * HIDC * 2;
constexpr size_t SZ_X2H  = (size_t)NN * F_OUT * 2;
constexpr size_t SZ_EH   = (size_t)MM * F_OUT * 2;
constexpr size_t SZ_WT1  = (size_t)HIDC * F_IN * 2;   // W1^T fp16 [256][128]
constexpr size_t SZ_WT2  = (size_t)F_OUT * HIDC * 2;  // W2^T fp16 [128][256]
constexpr size_t SZ_DEGN = (size_t)NN * 4;
constexpr size_t SZ_DEGM = (size_t)MM * 4;
constexpr size_t SZ_OFFN = (size_t)NN * 4;
constexpr size_t SZ_OFFM = (size_t)MM * 4;
constexpr size_t SZ_CURN = (size_t)NN * 4;
constexpr size_t SZ_CURM = (size_t)MM * 4;
constexpr size_t SZ_DINV = (size_t)NN * 4;
constexpr size_t SZ_BINV = (size_t)MM * 4;
constexpr size_t SZ_NE   = (size_t)NNZV * 4;
constexpr size_t SZ_EN   = (size_t)NNZV * 4;
constexpr size_t SZ_BS   = 256 * 4;
constexpr size_t SZ_BP   = 256 * 4;

constexpr size_t OFF_XH   = 0;
constexpr size_t OFF_T1H  = OFF_XH + SZ_XH;
constexpr size_t OFF_T2H  = OFF_T1H + SZ_T1H;
constexpr size_t OFF_HH   = OFF_T2H + SZ_T2H;
constexpr size_t OFF_X2H  = OFF_HH + SZ_HH;
constexpr size_t OFF_EH   = OFF_X2H + SZ_X2H;
constexpr size_t OFF_WT1  = OFF_EH + SZ_EH;
constexpr size_t OFF_WT2  = OFF_WT1 + SZ_WT1;
constexpr size_t OFF_DEGN = OFF_WT2 + SZ_WT2;
constexpr size_t OFF_DEGM = OFF_DEGN + SZ_DEGN;
constexpr size_t OFF_OFFN = OFF_DEGM + SZ_DEGM;
constexpr size_t OFF_OFFM = OFF_OFFN + SZ_OFFN;
constexpr size_t OFF_CURN = OFF_OFFM + SZ_OFFM;
constexpr size_t OFF_CURM = OFF_CURN + SZ_CURN;
constexpr size_t OFF_DINV = OFF_CURM + SZ_CURM;
constexpr size_t OFF_BINV = OFF_DINV + SZ_DINV;
constexpr size_t OFF_NE   = OFF_BINV + SZ_BINV;
constexpr size_t OFF_EN   = OFF_NE + SZ_NE;
constexpr size_t OFF_BS   = OFF_EN + SZ_EN;
constexpr size_t OFF_BP   = OFF_BS + SZ_BS;
constexpr size_t SCRATCH_TOTAL = OFF_BP + SZ_BP;

__device__ __align__(256) unsigned char g_scratch[SCRATCH_TOTAL];

__device__ __forceinline__ float* scrF(size_t off) {
    return reinterpret_cast<float*>(g_scratch + off);
}
__device__ __forceinline__ int* scrI(size_t off) {
    return reinterpret_cast<int*>(g_scratch + off);
}
__device__ __forceinline__ __half* scrH(size_t off) {
    return reinterpret_cast<__half*>(g_scratch + off);
}

__device__ __forceinline__ uint32_t smem_u32(const void* p) {
    uint32_t a;
    asm("{ .reg .u64 t; cvta.to.shared.u64 t, %1; cvt.u32.u64 %0, t; }"
        : "=r"(a) : "l"(p));
    return a;
}
__device__ __forceinline__ void ldsm_x4(uint32_t& r0, uint32_t& r1,
                                        uint32_t& r2, uint32_t& r3,
                                        uint32_t addr) {
    asm volatile("ldmatrix.sync.aligned.m8n8.x4.shared.b16 {%0,%1,%2,%3}, [%4];"
                 : "=r"(r0), "=r"(r1), "=r"(r2), "=r"(r3) : "r"(addr));
}
__device__ __forceinline__ void mma16816(float* c, const uint32_t* a,
                                         uint32_t b0, uint32_t b1) {
    asm volatile(
        "mma.sync.aligned.m16n8k16.row.col.f32.f16.f16.f32 "
        "{%0,%1,%2,%3}, {%4,%5,%6,%7}, {%8,%9}, {%0,%1,%2,%3};"
        : "+f"(c[0]), "+f"(c[1]), "+f"(c[2]), "+f"(c[3])
        : "r"(a[0]), "r"(a[1]), "r"(a[2]), "r"(a[3]), "r"(b0), "r"(b1));
}

// ---------------------------------------------------------------------------
// CSR build (unchanged)
// ---------------------------------------------------------------------------
__global__ void zero_deg_kernel() {
    int i = blockIdx.x * blockDim.x + threadIdx.x;
    int* degN = scrI(OFF_DEGN);
    int* degM = scrI(OFF_DEGM);
    if (i < NN) degN[i] = 0;
    if (i < MM) degM[i] = 0;
}

__global__ void count_deg_kernel(const int* __restrict__ node_idx,
                                 const int* __restrict__ edge_idx) {
    int* degN = scrI(OFF_DEGN);
    int* degM = scrI(OFF_DEGM);
    int stride = gridDim.x * blockDim.x;
    for (int i = blockIdx.x * blockDim.x + threadIdx.x; i < NNZV; i += stride) {
        atomicAdd(&degN[node_idx[i]], 1);
        atomicAdd(&degM[edge_idx[i]], 1);
    }
}

constexpr int SC_ELEMS = 1024;
constexpr int NBLK_N = (NN + SC_ELEMS - 1) / SC_ELEMS;   // 49
constexpr int NBLK_M = (MM + SC_ELEMS - 1) / SC_ELEMS;   // 25
constexpr int NBLK_T = NBLK_N + NBLK_M;                  // 74

__global__ __launch_bounds__(256) void scanA_kernel() {
    int blk = blockIdx.x;
    const int* deg;
    int n, b;
    if (blk < NBLK_N) { deg = scrI(OFF_DEGN); n = NN; b = blk; }
    else              { deg = scrI(OFF_DEGM); n = MM; b = blk - NBLK_N; }
    int tid = threadIdx.x;
    int base = b * SC_ELEMS + tid * 4;
    int s = 0;
    #pragma unroll
    for (int j = 0; j < 4; j++) {
        int i = base + j;
        if (i < n) s += deg[i];
    }
    __shared__ int wsum[8];
    for (int d2 = 16; d2 > 0; d2 >>= 1) s += __shfl_down_sync(0xffffffffu, s, d2);
    if ((tid & 31) == 0) wsum[tid >> 5] = s;
    __syncthreads();
    if (tid < 8) {
        int v = wsum[tid];
        for (int d2 = 4; d2 > 0; d2 >>= 1) v += __shfl_down_sync(0xffu, v, d2);
        if (tid == 0) scrI(OFF_BS)[blk] = v;
    }
}

__global__ void scanB_kernel() {
    __shared__ int sh[128];
    int tid = threadIdx.x;
    const int* bs = scrI(OFF_BS);
    sh[tid] = (tid < NBLK_T) ? bs[tid] : 0;
    __syncthreads();
    for (int d = 1; d < 128; d <<= 1) {
        int v = (tid >= d) ? sh[tid - d] : 0;
        __syncthreads();
        sh[tid] += v;
        __syncthreads();
    }
    if (tid < NBLK_T) {
        int pre = (tid == 0) ? 0 : sh[tid - 1];
        if (tid >= NBLK_N) pre -= sh[NBLK_N - 1];
        scrI(OFF_BP)[tid] = pre;
    }
}

__global__ __launch_bounds__(256) void scanC_kernel() {
    int blk = blockIdx.x;
    const int* deg; int* off; int* cur; float* inv;
    int n, b;
    if (blk < NBLK_N) {
        deg = scrI(OFF_DEGN); off = scrI(OFF_OFFN); cur = scrI(OFF_CURN);
        inv = scrF(OFF_DINV); n = NN; b = blk;
    } else {
        deg = scrI(OFF_DEGM); off = scrI(OFF_OFFM); cur = scrI(OFF_CURM);
        inv = scrF(OFF_BINV); n = MM; b = blk - NBLK_N;
    }
    int tid = threadIdx.x;
    int base = b * SC_ELEMS + tid * 4;
    int d[4];
    int s = 0;
    #pragma unroll
    for (int j = 0; j < 4; j++) {
        int i = base + j;
        d[j] = (i < n) ? deg[i] : 0;
        s += d[j];
    }
    __shared__ int sh[256];
    sh[tid] = s;
    __syncthreads();
    for (int dd = 1; dd < 256; dd <<= 1) {
        int v = (tid >= dd) ? sh[tid - dd] : 0;
        __syncthreads();
        sh[tid] += v;
        __syncthreads();
    }
    int run = scrI(OFF_BP)[blk] + ((tid == 0) ? 0 : sh[tid - 1]);
    #pragma unroll
    for (int j = 0; j < 4; j++) {
        int i = base + j;
        if (i < n) {
            off[i] = run;
            cur[i] = run;
            inv[i] = (d[j] > 0) ? (1.0f / (float)d[j]) : 0.0f;
            run += d[j];
        }
    }
}

__global__ void fill_csr_kernel(const int* __restrict__ node_idx,
                                const int* __restrict__ edge_idx) {
    int* curN = scrI(OFF_CURN);
    int* curM = scrI(OFF_CURM);
    int* nodeEdges = scrI(OFF_NE);
    int* edgeNodes = scrI(OFF_EN);
    int stride = gridDim.x * blockDim.x;
    for (int i = blockIdx.x * blockDim.x + threadIdx.x; i < NNZV; i += stride) {
        int n = node_idx[i];
        int m = edge_idx[i];
        int p = atomicAdd(&curN[n], 1);
        nodeEdges[p] = m;
        int q = atomicAdd(&curM[m], 1);
        edgeNodes[q] = n;
    }
}

// ---------------------------------------------------------------------------
// Prep: x fp32 -> fp16; W1/W2 -> K-major fp16 transposes
// ---------------------------------------------------------------------------
__global__ __launch_bounds__(256) void conv_f2h_kernel(const float4* __restrict__ x) {
    uint2* xh = reinterpret_cast<uint2*>(g_scratch + OFF_XH);
    int stride = gridDim.x * blockDim.x;
    for (int i = blockIdx.x * blockDim.x + threadIdx.x; i < NN * 32; i += stride) {
        float4 v = __ldg(&x[i]);
        __half2 h01 = __floats2half2_rn(v.x, v.y);
        __half2 h23 = __floats2half2_rn(v.z, v.w);
        uint2 o;
        o.x = *reinterpret_cast<uint32_t*>(&h01);
        o.y = *reinterpret_cast<uint32_t*>(&h23);
        xh[i] = o;
    }
}

__global__ __launch_bounds__(256) void prep_wt_kernel(
    const float* __restrict__ W1, const float* __restrict__ W2)
{
    int i = blockIdx.x * blockDim.x + threadIdx.x;
    __half* wt1 = scrH(OFF_WT1);
    __half* wt2 = scrH(OFF_WT2);
    if (i < HIDC * F_IN) {          // wt1[n][k] = W1[k][n]
        int n = i / F_IN, k = i % F_IN;
        wt1[i] = __float2half(W1[k * HIDC + n]);
    }
    if (i < F_OUT * HIDC) {         // wt2[n][k] = W2[k][n]
        int n = i / HIDC, k = i % HIDC;
        wt2[i] = __float2half(W2[k * F_OUT + n]);
    }
}

// ---------------------------------------------------------------------------
// Gather-reduce over fp16 sources (C = 128). 16 lanes/row, uint4 loads.
// ---------------------------------------------------------------------------
template<bool HAS_BIAS, bool OUT_F, bool OUT_H>
__global__ void gather_h_kernel(size_t srcOff,
                                float* dstFext, size_t dstFOff,
                                size_t dstHOff,
                                size_t offOff, size_t degOff,
                                size_t lstOff, size_t invOff,
                                const float* __restrict__ bias,
                                int nrows)
{
    const uint4* __restrict__ src =
        reinterpret_cast<const uint4*>(g_scratch + srcOff);
    const int* __restrict__ off = scrI(offOff);
    const int* __restrict__ deg = scrI(degOff);
    const int* __restrict__ lst = scrI(lstOff);
    const float* __restrict__ inv = scrF(invOff);

    int row = blockIdx.x * blockDim.y + threadIdx.y;
    if (row >= nrows) return;
    int tx = threadIdx.x;   // 0..15
    int o = off[row];
    int d = deg[row];

    float a0 = 0.f, a1 = 0.f, a2 = 0.f, a3 = 0.f;
    float a4 = 0.f, a5 = 0.f, a6 = 0.f, a7 = 0.f;

    int j = 0;
    for (; j + 4 <= d; j += 4) {
        int i0 = __ldg(&lst[o + j + 0]);
        int i1 = __ldg(&lst[o + j + 1]);
        int i2 = __ldg(&lst[o + j + 2]);
        int i3 = __ldg(&lst[o + j + 3]);
        uint4 v0 = __ldg(&src[(size_t)i0 * 16 + tx]);
        uint4 v1 = __ldg(&src[(size_t)i1 * 16 + tx]);
        uint4 v2 = __ldg(&src[(size_t)i2 * 16 + tx]);
        uint4 v3 = __ldg(&src[(size_t)i3 * 16 + tx]);
        float2 f;
        f = __half22float2(*reinterpret_cast<__half2*>(&v0.x)); a0 += f.x; a1 += f.y;
        f = __half22float2(*reinterpret_cast<__half2*>(&v0.y)); a2 += f.x; a3 += f.y;
        f = __half22float2(*reinterpret_cast<__half2*>(&v0.z)); a4 += f.x; a5 += f.y;
        f = __half22float2(*reinterpret_cast<__half2*>(&v0.w)); a6 += f.x; a7 += f.y;
        f = __half22float2(*reinterpret_cast<__half2*>(&v1.x)); a0 += f.x; a1 += f.y;
        f = __half22float2(*reinterpret_cast<__half2*>(&v1.y)); a2 += f.x; a3 += f.y;
        f = __half22float2(*reinterpret_cast<__half2*>(&v1.z)); a4 += f.x; a5 += f.y;
        f = __half22float2(*reinterpret_cast<__half2*>(&v1.w)); a6 += f.x; a7 += f.y;
        f = __half22float2(*reinterpret_cast<__half2*>(&v2.x)); a0 += f.x; a1 += f.y;
        f = __half22float2(*reinterpret_cast<__half2*>(&v2.y)); a2 += f.x; a3 += f.y;
        f = __half22float2(*reinterpret_cast<__half2*>(&v2.z)); a4 += f.x; a5 += f.y;
        f = __half22float2(*reinterpret_cast<__half2*>(&v2.w)); a6 += f.x; a7 += f.y;
        f = __half22float2(*reinterpret_cast<__half2*>(&v3.x)); a0 += f.x; a1 += f.y;
        f = __half22float2(*reinterpret_cast<__half2*>(&v3.y)); a2 += f.x; a3 += f.y;
        f = __half22float2(*reinterpret_cast<__half2*>(&v3.z)); a4 += f.x; a5 += f.y;
        f = __half22float2(*reinterpret_cast<__half2*>(&v3.w)); a6 += f.x; a7 += f.y;
    }
    for (; j < d; j++) {
        int i0 = __ldg(&lst[o + j]);
        uint4 v0 = __ldg(&src[(size_t)i0 * 16 + tx]);
        float2 f;
        f = __half22float2(*reinterpret_cast<__half2*>(&v0.x)); a0 += f.x; a1 += f.y;
        f = __half22float2(*reinterpret_cast<__half2*>(&v0.y)); a2 += f.x; a3 += f.y;
        f = __half22float2(*reinterpret_cast<__half2*>(&v0.z)); a4 += f.x; a5 += f.y;
        f = __half22float2(*reinterpret_cast<__half2*>(&v0.w)); a6 += f.x; a7 += f.y;
    }

    float s = inv[row];
    a0 *= s; a1 *= s; a2 *= s; a3 *= s;
    a4 *= s; a5 *= s; a6 *= s; a7 *= s;
    if (HAS_BIAS) {
        const float4* b4 = reinterpret_cast<const float4*>(bias);
        float4 b0 = __ldg(&b4[tx * 2]);
        float4 b1 = __ldg(&b4[tx * 2 + 1]);
        a0 += b0.x; a1 += b0.y; a2 += b0.z; a3 += b0.w;
        a4 += b1.x; a5 += b1.y; a6 += b1.z; a7 += b1.w;
    }
    if (OUT_F) {
        float4* dstF = dstFext
            ? reinterpret_cast<float4*>(dstFext)
            : reinterpret_cast<float4*>(g_scratch + dstFOff);
        dstF[(size_t)row * 32 + tx * 2]     = make_float4(a0, a1, a2, a3);
        dstF[(size_t)row * 32 + tx * 2 + 1] = make_float4(a4, a5, a6, a7);
    }
    if (OUT_H) {
        uint4* dstH = reinterpret_cast<uint4*>(g_scratch + dstHOff);
        __half2 h0 = __floats2half2_rn(a0, a1);
        __half2 h1 = __floats2half2_rn(a2, a3);
        __half2 h2 = __floats2half2_rn(a4, a5);
        __half2 h3 = __floats2half2_rn(a6, a7);
        uint4 ov;
        ov.x = *reinterpret_cast<uint32_t*>(&h0);
        ov.y = *reinterpret_cast<uint32_t*>(&h1);
        ov.z = *reinterpret_cast<uint32_t*>(&h2);
        ov.w = *reinterpret_cast<uint32_t*>(&h3);
        dstH[(size_t)row * 16 + tx] = ov;
    }
}

// ---------------------------------------------------------------------------
// fp16 mma.sync GEMM: C[M,NCOLS](fp16) = A[M,K](fp16) @ WT[NCOLS,K]^T(fp16)
// 128x128 tile, BK=32, 8 warps (4M x 2N), warp tile 32x64, m16n8k16 frags
// via ldmatrix. Double-buffered smem with register prefetch.
// ---------------------------------------------------------------------------
template<int K, int NCOLS, bool HAS_BIAS, bool HAS_ELU>
__global__ __launch_bounds__(256) void gemm_mma_kernel(
    size_t aOff, size_t wtOff, size_t cOff,
    const float* __restrict__ bias, int Mrows)
{
    constexpr int NCHUNK = K / 32;
    constexpr int RS = 40;                // halves per smem row (padded)
    __shared__ __align__(1024) __half As[2][128][RS];
    __shared__ __align__(1024) __half Bs[2][128][RS];

    const __half* __restrict__ A  = scrH(aOff);
    const __half* __restrict__ WT = scrH(wtOff);
    __half* __restrict__ C = scrH(cOff);

    int tid  = threadIdx.x;
    int lane = tid & 31;
    int warp = tid >> 5;
    int warpM = (warp & 3) * 32;
    int warpN = (warp >> 2) * 64;
    int rowBase = blockIdx.y * 128;
    int colBase = blockIdx.x * 128;

    int lrow  = tid >> 2;     // 0..63 (two passes -> 128 rows)
    int lcol8 = tid & 3;      // uint4 granule (8 halves)

    float acc[2][8][4];
    #pragma unroll
    for (int mt = 0; mt < 2; mt++)
        #pragma unroll
        for (int nt = 0; nt < 8; nt++)
            #pragma unroll
            for (int r = 0; r < 4; r++)
                acc[mt][nt][r] = 0.f;

    uint32_t laneRow = lane & 15;
    uint32_t laneK   = (lane >> 4) * 8;
    uint32_t asBase = smem_u32(&As[0][0][0]);
    uint32_t bsBase = smem_u32(&Bs[0][0][0]);
    constexpr uint32_t BUFB = 128 * RS * 2;   // bytes per buffer

    uint4 pa[2], pb[2];
    // preload chunk 0
    #pragma unroll
    for (int p = 0; p < 2; p++) {
        int row = p * 64 + lrow;
        int gm = rowBase + row;
        pa[p] = (gm < Mrows)
            ? *(const uint4*)&A[(size_t)gm * K + lcol8 * 8]
            : make_uint4(0u, 0u, 0u, 0u);
        pb[p] = *(const uint4*)&WT[(size_t)(colBase + row) * K + lcol8 * 8];
    }
    #pragma unroll
    for (int p = 0; p < 2; p++) {
        int row = p * 64 + lrow;
        *reinterpret_cast<uint4*>(&As[0][row][lcol8 * 8]) = pa[p];
        *reinterpret_cast<uint4*>(&Bs[0][row][lcol8 * 8]) = pb[p];
    }
    __syncthreads();

    for (int kc = 0; kc < NCHUNK; kc++) {
        int buf = kc & 1;
        bool more = (kc + 1 < NCHUNK);
        if (more) {
            int k0 = (kc + 1) * 32;
            #pragma unroll
            for (int p = 0; p < 2; p++) {
                int row = p * 64 + lrow;
                int gm = rowBase + row;
                pa[p] = (gm < Mrows)
                    ? *(const uint4*)&A[(size_t)gm * K + k0 + lcol8 * 8]
                    : make_uint4(0u, 0u, 0u, 0u);
                pb[p] = *(const uint4*)&WT[(size_t)(colBase + row) * K + k0 + lcol8 * 8];
            }
        }

        uint32_t aBufBase = asBase + (uint32_t)buf * BUFB;
        uint32_t bBufBase = bsBase + (uint32_t)buf * BUFB;
        #pragma unroll
        for (int ks = 0; ks < 2; ks++) {
            uint32_t k0 = ks * 16 + laneK;
            uint32_t af[2][4];
            #pragma unroll
            for (int mt = 0; mt < 2; mt++) {
                uint32_t addr = aBufBase +
                    ((warpM + mt * 16 + laneRow) * RS + k0) * 2;
                ldsm_x4(af[mt][0], af[mt][1], af[mt][2], af[mt][3], addr);
            }
            #pragma unroll
            for (int ng = 0; ng < 4; ng++) {
                uint32_t addr = bBufBase +
                    ((warpN + ng * 16 + laneRow) * RS + k0) * 2;
                uint32_t b0, b1, b2, b3;
                ldsm_x4(b0, b1, b2, b3, addr);
                #pragma unroll
                for (int mt = 0; mt < 2; mt++) {
                    mma16816(acc[mt][ng * 2],     af[mt], b0, b2);
                    mma16816(acc[mt][ng * 2 + 1], af[mt], b1, b3);
                }
            }
        }

        if (more) {
            int nb = buf ^ 1;
            #pragma unroll
            for (int p = 0; p < 2; p++) {
                int row = p * 64 + lrow;
                *reinterpret_cast<uint4*>(&As[nb][row][lcol8 * 8]) = pa[p];
                *reinterpret_cast<uint4*>(&Bs[nb][row][lcol8 * 8]) = pb[p];
            }
        }
        __syncthreads();
    }

    // Epilogue: fp32 acc -> (bias, ELU) -> fp16 store (2 halves per 4B)
    #pragma unroll
    for (int nt = 0; nt < 8; nt++) {
        int c = colBase + warpN + nt * 8 + (lane & 3) * 2;
        float b0 = 0.f, b1 = 0.f;
        if (HAS_BIAS) {
            b0 = __ldg(&bias[c]);
            b1 = __ldg(&bias[c + 1]);
        }
        #pragma unroll
        for (int mt = 0; mt < 2; mt++) {
            int r = rowBase + warpM + mt * 16 + (lane >> 2);
            float v0 = acc[mt][nt][0] + b0;
            float v1 = acc[mt][nt][1] + b1;
            float v2 = acc[mt][nt][2] + b0;
            float v3 = acc[mt][nt][3] + b1;
            if (HAS_ELU) {
                v0 = (v0 > 0.f) ? v0 : expm1f(v0);
                v1 = (v1 > 0.f) ? v1 : expm1f(v1);
                v2 = (v2 > 0.f) ? v2 : expm1f(v2);
                v3 = (v3 > 0.f) ? v3 : expm1f(v3);
            }
            if (r < Mrows) {
                __half2 h = __floats2half2_rn(v0, v1);
                *reinterpret_cast<uint32_t*>(&C[(size_t)r * NCOLS + c]) =
                    *reinterpret_cast<uint32_t*>(&h);
            }
            if (r + 8 < Mrows) {
                __half2 h = __floats2half2_rn(v2, v3);
                *reinterpret_cast<uint32_t*>(&C[(size_t)(r + 8) * NCOLS + c]) =
                    *reinterpret_cast<uint32_t*>(&h);
            }
        }
    }
}

// ---------------------------------------------------------------------------
// Launch: kernel launches ONLY.
// ---------------------------------------------------------------------------
extern "C" void kernel_launch(void* const* d_in, const int* in_sizes, int n_in,
                              void* d_out, int out_size)
{
    const float* x        = (const float*)d_in[0];
    const float* W1       = (const float*)d_in[1];
    const float* b1       = (const float*)d_in[2];
    const float* W2       = (const float*)d_in[3];
    const float* b2       = (const float*)d_in[4];
    const int*   node_idx = (const int*)d_in[5];
    const int*   edge_idx = (const int*)d_in[6];

    float* out   = (float*)d_out;
    float* e_out = out + (size_t)NN * F_OUT;

    // ---- CSR build + prep ----
    zero_deg_kernel<<<(NN + 255) / 256, 256>>>();
    conv_f2h_kernel<<<1024, 256>>>((const float4*)x);
    prep_wt_kernel<<<(HIDC * F_IN + 255) / 256, 256>>>(W1, W2);
    count_deg_kernel<<<2048, 256>>>(node_idx, edge_idx);
    scanA_kernel<<<NBLK_T, 256>>>();
    scanB_kernel<<<1, 128>>>();
    scanC_kernel<<<NBLK_T, 256>>>();
    fill_csr_kernel<<<2048, 256>>>(node_idx, edge_idx);

    dim3 gblk(16, 16);

    // ---- Layer 1 (GEMM commuted past both segment-sums) ----
    gather_h_kernel<false, false, true><<<(MM + 15) / 16, gblk>>>(
        OFF_XH, nullptr, 0, OFF_T1H,
        OFF_OFFM, OFF_DEGM, OFF_EN, OFF_BINV, nullptr, MM);
    gather_h_kernel<false, false, true><<<(NN + 15) / 16, gblk>>>(
        OFF_T1H, nullptr, 0, OFF_T2H,
        OFF_OFFN, OFF_DEGN, OFF_NE, OFF_DINV, nullptr, NN);
    // hh = elu(t2h @ W1 + b1)   fp16 out   [50000,128]x[128,256]
    {
        dim3 grid(HIDC / 128, (NN + 127) / 128);
        gemm_mma_kernel<F_IN, HIDC, true, true><<<grid, 256>>>(
            OFF_T2H, OFF_WT1, OFF_HH, b1, NN);
    }

    // ---- Layer 2 ----
    // x2h = hh @ W2   fp16 out  [50000,256]x[256,128]
    {
        dim3 grid(F_OUT / 128, (NN + 127) / 128);
        gemm_mma_kernel<HIDC, F_OUT, false, false><<<grid, 256>>>(
            OFF_HH, OFF_WT2, OFF_X2H, nullptr, NN);
    }
    // e_out[m] (fp32, returned) + eh[m] (fp16 copy)
    gather_h_kernel<false, true, true><<<(MM + 15) / 16, gblk>>>(
        OFF_X2H, e_out, 0, OFF_EH,
        OFF_OFFM, OFF_DEGM, OFF_EN, OFF_BINV, nullptr, MM);
    // out[n] = Dinv[n] * sum eh[m] + b2
    gather_h_kernel<true, true, false><<<(NN + 15) / 16, gblk>>>(
        OFF_EH, out, 0, 0,
        OFF_OFFN, OFF_DEGN, OFF_NE, OFF_DINV, b2, NN);
}

// round 10
// speedup vs baseline: 2.7967x; 1.0643x over previous
#include <cuda_runtime.h>
#include <cuda_fp16.h>
#include <cstdint>

#define NN   50000
#define MM   25000
#define NNZV 800000
#define F_IN 128
#define HIDC 256
#define F_OUT 128

// ---------------------------------------------------------------------------
// Scratch (fp16 activation chain end-to-end)
// ---------------------------------------------------------------------------
constexpr size_t SZ_XH   = (size_t)NN * F_IN * 2;
constexpr size_t SZ_T1H  = (size_t)MM * F_IN * 2;
constexpr size_t SZ_T2H  = (size_t)NN * F_IN * 2;
constexpr size_t SZ_HH   = (size_t)NN * HIDC * 2;
constexpr size_t SZ_X2H  = (size_t)NN * F_OUT * 2;
constexpr size_t SZ_EH   = (size_t)MM * F_OUT * 2;
constexpr size_t SZ_WT1  = (size_t)HIDC * F_IN * 2;
constexpr size_t SZ_WT2  = (size_t)F_OUT * HIDC * 2;
constexpr size_t SZ_DEGN = (size_t)NN * 4;
constexpr size_t SZ_DEGM = (size_t)MM * 4;
constexpr size_t SZ_OFFN = (size_t)NN * 4;
constexpr size_t SZ_OFFM = (size_t)MM * 4;
constexpr size_t SZ_DINV = (size_t)NN * 4;
constexpr size_t SZ_BINV = (size_t)MM * 4;
constexpr size_t SZ_NE   = (size_t)NNZV * 4;
constexpr size_t SZ_EN   = (size_t)NNZV * 4;
constexpr size_t SZ_RKN  = (size_t)NNZV * 4;   // per-nnz rank within node seg
constexpr size_t SZ_RKM  = (size_t)NNZV * 4;   // per-nnz rank within edge seg
constexpr size_t SZ_BS   = 256 * 4;
constexpr size_t SZ_BP   = 256 * 4;

constexpr size_t OFF_XH   = 0;
constexpr size_t OFF_T1H  = OFF_XH + SZ_XH;
constexpr size_t OFF_T2H  = OFF_T1H + SZ_T1H;
constexpr size_t OFF_HH   = OFF_T2H + SZ_T2H;
constexpr size_t OFF_X2H  = OFF_HH + SZ_HH;
constexpr size_t OFF_EH   = OFF_X2H + SZ_X2H;
constexpr size_t OFF_WT1  = OFF_EH + SZ_EH;
constexpr size_t OFF_WT2  = OFF_WT1 + SZ_WT1;
constexpr size_t OFF_DEGN = OFF_WT2 + SZ_WT2;
constexpr size_t OFF_DEGM = OFF_DEGN + SZ_DEGN;
constexpr size_t OFF_OFFN = OFF_DEGM + SZ_DEGM;
constexpr size_t OFF_OFFM = OFF_OFFN + SZ_OFFN;
constexpr size_t OFF_DINV = OFF_OFFM + SZ_OFFM;
constexpr size_t OFF_BINV = OFF_DINV + SZ_DINV;
constexpr size_t OFF_NE   = OFF_BINV + SZ_BINV;
constexpr size_t OFF_EN   = OFF_NE + SZ_NE;
constexpr size_t OFF_RKN  = OFF_EN + SZ_EN;
constexpr size_t OFF_RKM  = OFF_RKN + SZ_RKN;
constexpr size_t OFF_BS   = OFF_RKM + SZ_RKM;
constexpr size_t OFF_BP   = OFF_BS + SZ_BS;
constexpr size_t SCRATCH_TOTAL = OFF_BP + SZ_BP;

__device__ __align__(256) unsigned char g_scratch[SCRATCH_TOTAL];

__device__ __forceinline__ float* scrF(size_t off) {
    return reinterpret_cast<float*>(g_scratch + off);
}
__device__ __forceinline__ int* scrI(size_t off) {
    return reinterpret_cast<int*>(g_scratch + off);
}
__device__ __forceinline__ __half* scrH(size_t off) {
    return reinterpret_cast<__half*>(g_scratch + off);
}

__device__ __forceinline__ uint32_t smem_u32(const void* p) {
    uint32_t a;
    asm("{ .reg .u64 t; cvta.to.shared.u64 t, %1; cvt.u32.u64 %0, t; }"
        : "=r"(a) : "l"(p));
    return a;
}
__device__ __forceinline__ void ldsm_x4(uint32_t& r0, uint32_t& r1,
                                        uint32_t& r2, uint32_t& r3,
                                        uint32_t addr) {
    asm volatile("ldmatrix.sync.aligned.m8n8.x4.shared.b16 {%0,%1,%2,%3}, [%4];"
                 : "=r"(r0), "=r"(r1), "=r"(r2), "=r"(r3) : "r"(addr));
}
__device__ __forceinline__ void mma16816(float* c, const uint32_t* a,
                                         uint32_t b0, uint32_t b1) {
    asm volatile(
        "mma.sync.aligned.m16n8k16.row.col.f32.f16.f16.f32 "
        "{%0,%1,%2,%3}, {%4,%5,%6,%7}, {%8,%9}, {%0,%1,%2,%3};"
        : "+f"(c[0]), "+f"(c[1]), "+f"(c[2]), "+f"(c[3])
        : "r"(a[0]), "r"(a[1]), "r"(a[2]), "r"(a[3]), "r"(b0), "r"(b1));
}

// ---------------------------------------------------------------------------
// CSR build
// ---------------------------------------------------------------------------
__global__ void zero_deg_kernel() {
    int i = blockIdx.x * blockDim.x + threadIdx.x;
    int* degN = scrI(OFF_DEGN);
    int* degM = scrI(OFF_DEGM);
    if (i < NN) degN[i] = 0;
    if (i < MM) degM[i] = 0;
}

// Count degrees AND record each entry's rank within its segment.
__global__ void count_deg_kernel(const int* __restrict__ node_idx,
                                 const int* __restrict__ edge_idx) {
    int* degN = scrI(OFF_DEGN);
    int* degM = scrI(OFF_DEGM);
    int* rkN  = scrI(OFF_RKN);
    int* rkM  = scrI(OFF_RKM);
    int stride = gridDim.x * blockDim.x;
    for (int i = blockIdx.x * blockDim.x + threadIdx.x; i < NNZV; i += stride) {
        rkN[i] = atomicAdd(&degN[node_idx[i]], 1);
        rkM[i] = atomicAdd(&degM[edge_idx[i]], 1);
    }
}

constexpr int SC_ELEMS = 1024;
constexpr int NBLK_N = (NN + SC_ELEMS - 1) / SC_ELEMS;   // 49
constexpr int NBLK_M = (MM + SC_ELEMS - 1) / SC_ELEMS;   // 25
constexpr int NBLK_T = NBLK_N + NBLK_M;                  // 74

__global__ __launch_bounds__(256) void scanA_kernel() {
    int blk = blockIdx.x;
    const int* deg;
    int n, b;
    if (blk < NBLK_N) { deg = scrI(OFF_DEGN); n = NN; b = blk; }
    else              { deg = scrI(OFF_DEGM); n = MM; b = blk - NBLK_N; }
    int tid = threadIdx.x;
    int base = b * SC_ELEMS + tid * 4;
    int s = 0;
    #pragma unroll
    for (int j = 0; j < 4; j++) {
        int i = base + j;
        if (i < n) s += deg[i];
    }
    __shared__ int wsum[8];
    for (int d2 = 16; d2 > 0; d2 >>= 1) s += __shfl_down_sync(0xffffffffu, s, d2);
    if ((tid & 31) == 0) wsum[tid >> 5] = s;
    __syncthreads();
    if (tid < 8) {
        int v = wsum[tid];
        for (int d2 = 4; d2 > 0; d2 >>= 1) v += __shfl_down_sync(0xffu, v, d2);
        if (tid == 0) scrI(OFF_BS)[blk] = v;
    }
}

__global__ void scanB_kernel() {
    __shared__ int sh[128];
    int tid = threadIdx.x;
    const int* bs = scrI(OFF_BS);
    sh[tid] = (tid < NBLK_T) ? bs[tid] : 0;
    __syncthreads();
    for (int d = 1; d < 128; d <<= 1) {
        int v = (tid >= d) ? sh[tid - d] : 0;
        __syncthreads();
        sh[tid] += v;
        __syncthreads();
    }
    if (tid < NBLK_T) {
        int pre = (tid == 0) ? 0 : sh[tid - 1];
        if (tid >= NBLK_N) pre -= sh[NBLK_N - 1];
        scrI(OFF_BP)[tid] = pre;
    }
}

__global__ __launch_bounds__(256) void scanC_kernel() {
    int blk = blockIdx.x;
    const int* deg; int* off; float* inv;
    int n, b;
    if (blk < NBLK_N) {
        deg = scrI(OFF_DEGN); off = scrI(OFF_OFFN);
        inv = scrF(OFF_DINV); n = NN; b = blk;
    } else {
        deg = scrI(OFF_DEGM); off = scrI(OFF_OFFM);
        inv = scrF(OFF_BINV); n = MM; b = blk - NBLK_N;
    }
    int tid = threadIdx.x;
    int base = b * SC_ELEMS + tid * 4;
    int d[4];
    int s = 0;
    #pragma unroll
    for (int j = 0; j < 4; j++) {
        int i = base + j;
        d[j] = (i < n) ? deg[i] : 0;
        s += d[j];
    }
    __shared__ int sh[256];
    sh[tid] = s;
    __syncthreads();
    for (int dd = 1; dd < 256; dd <<= 1) {
        int v = (tid >= dd) ? sh[tid - dd] : 0;
        __syncthreads();
        sh[tid] += v;
        __syncthreads();
    }
    int run = scrI(OFF_BP)[blk] + ((tid == 0) ? 0 : sh[tid - 1]);
    #pragma unroll
    for (int j = 0; j < 4; j++) {
        int i = base + j;
        if (i < n) {
            off[i] = run;
            inv[i] = (d[j] > 0) ? (1.0f / (float)d[j]) : 0.0f;
            run += d[j];
        }
    }
}

// Atomic-free fill: position = off[seg] + saved rank.
__global__ void fill_csr_kernel(const int* __restrict__ node_idx,
                                const int* __restrict__ edge_idx) {
    const int* offN = scrI(OFF_OFFN);
    const int* offM = scrI(OFF_OFFM);
    const int* rkN  = scrI(OFF_RKN);
    const int* rkM  = scrI(OFF_RKM);
    int* nodeEdges = scrI(OFF_NE);
    int* edgeNodes = scrI(OFF_EN);
    int stride = gridDim.x * blockDim.x;
    for (int i = blockIdx.x * blockDim.x + threadIdx.x; i < NNZV; i += stride) {
        int n = node_idx[i];
        int m = edge_idx[i];
        nodeEdges[offN[n] + rkN[i]] = m;
        edgeNodes[offM[m] + rkM[i]] = n;
    }
}

// ---------------------------------------------------------------------------
// Prep: x fp32 -> fp16; W1/W2 -> K-major fp16 transposes
// ---------------------------------------------------------------------------
__global__ __launch_bounds__(256) void conv_f2h_kernel(const float4* __restrict__ x) {
    uint2* xh = reinterpret_cast<uint2*>(g_scratch + OFF_XH);
    int stride = gridDim.x * blockDim.x;
    for (int i = blockIdx.x * blockDim.x + threadIdx.x; i < NN * 32; i += stride) {
        float4 v = __ldg(&x[i]);
        __half2 h01 = __floats2half2_rn(v.x, v.y);
        __half2 h23 = __floats2half2_rn(v.z, v.w);
        uint2 o;
        o.x = *reinterpret_cast<uint32_t*>(&h01);
        o.y = *reinterpret_cast<uint32_t*>(&h23);
        xh[i] = o;
    }
}

__global__ __launch_bounds__(256) void prep_wt_kernel(
    const float* __restrict__ W1, const float* __restrict__ W2)
{
    int i = blockIdx.x * blockDim.x + threadIdx.x;
    __half* wt1 = scrH(OFF_WT1);
    __half* wt2 = scrH(OFF_WT2);
    if (i < HIDC * F_IN) {
        int n = i / F_IN, k = i % F_IN;
        wt1[i] = __float2half(W1[k * HIDC + n]);
    }
    if (i < F_OUT * HIDC) {
        int n = i / HIDC, k = i % HIDC;
        wt2[i] = __float2half(W2[k * F_OUT + n]);
    }
}

// ---------------------------------------------------------------------------
// Gather-reduce over fp16 sources (C = 128). 16 lanes/row, uint4 loads,
// unroll-8 main loop for deeper MLP.
// ---------------------------------------------------------------------------
template<bool HAS_BIAS, bool OUT_F, bool OUT_H>
__global__ void gather_h_kernel(size_t srcOff,
                                float* dstFext, size_t dstFOff,
                                size_t dstHOff,
                                size_t offOff, size_t degOff,
                                size_t lstOff, size_t invOff,
                                const float* __restrict__ bias,
                                int nrows)
{
    const uint4* __restrict__ src =
        reinterpret_cast<const uint4*>(g_scratch + srcOff);
    const int* __restrict__ off = scrI(offOff);
    const int* __restrict__ deg = scrI(degOff);
    const int* __restrict__ lst = scrI(lstOff);
    const float* __restrict__ inv = scrF(invOff);

    int row = blockIdx.x * blockDim.y + threadIdx.y;
    if (row >= nrows) return;
    int tx = threadIdx.x;   // 0..15
    int o = off[row];
    int d = deg[row];

    float a0 = 0.f, a1 = 0.f, a2 = 0.f, a3 = 0.f;
    float a4 = 0.f, a5 = 0.f, a6 = 0.f, a7 = 0.f;

    int j = 0;
    for (; j + 8 <= d; j += 8) {
        int idx[8];
        #pragma unroll
        for (int q = 0; q < 8; q++) idx[q] = __ldg(&lst[o + j + q]);
        uint4 v[8];
        #pragma unroll
        for (int q = 0; q < 8; q++) v[q] = __ldg(&src[(size_t)idx[q] * 16 + tx]);
        #pragma unroll
        for (int q = 0; q < 8; q++) {
            float2 f;
            f = __half22float2(*reinterpret_cast<__half2*>(&v[q].x)); a0 += f.x; a1 += f.y;
            f = __half22float2(*reinterpret_cast<__half2*>(&v[q].y)); a2 += f.x; a3 += f.y;
            f = __half22float2(*reinterpret_cast<__half2*>(&v[q].z)); a4 += f.x; a5 += f.y;
            f = __half22float2(*reinterpret_cast<__half2*>(&v[q].w)); a6 += f.x; a7 += f.y;
        }
    }
    if (j + 4 <= d) {
        int idx[4];
        #pragma unroll
        for (int q = 0; q < 4; q++) idx[q] = __ldg(&lst[o + j + q]);
        uint4 v[4];
        #pragma unroll
        for (int q = 0; q < 4; q++) v[q] = __ldg(&src[(size_t)idx[q] * 16 + tx]);
        #pragma unroll
        for (int q = 0; q < 4; q++) {
            float2 f;
            f = __half22float2(*reinterpret_cast<__half2*>(&v[q].x)); a0 += f.x; a1 += f.y;
            f = __half22float2(*reinterpret_cast<__half2*>(&v[q].y)); a2 += f.x; a3 += f.y;
            f = __half22float2(*reinterpret_cast<__half2*>(&v[q].z)); a4 += f.x; a5 += f.y;
            f = __half22float2(*reinterpret_cast<__half2*>(&v[q].w)); a6 += f.x; a7 += f.y;
        }
        j += 4;
    }
    for (; j < d; j++) {
        int i0 = __ldg(&lst[o + j]);
        uint4 v0 = __ldg(&src[(size_t)i0 * 16 + tx]);
        float2 f;
        f = __half22float2(*reinterpret_cast<__half2*>(&v0.x)); a0 += f.x; a1 += f.y;
        f = __half22float2(*reinterpret_cast<__half2*>(&v0.y)); a2 += f.x; a3 += f.y;
        f = __half22float2(*reinterpret_cast<__half2*>(&v0.z)); a4 += f.x; a5 += f.y;
        f = __half22float2(*reinterpret_cast<__half2*>(&v0.w)); a6 += f.x; a7 += f.y;
    }

    float s = inv[row];
    a0 *= s; a1 *= s; a2 *= s; a3 *= s;
    a4 *= s; a5 *= s; a6 *= s; a7 *= s;
    if (HAS_BIAS) {
        const float4* b4 = reinterpret_cast<const float4*>(bias);
        float4 b0 = __ldg(&b4[tx * 2]);
        float4 b1 = __ldg(&b4[tx * 2 + 1]);
        a0 += b0.x; a1 += b0.y; a2 += b0.z; a3 += b0.w;
        a4 += b1.x; a5 += b1.y; a6 += b1.z; a7 += b1.w;
    }
    if (OUT_F) {
        float4* dstF = dstFext
            ? reinterpret_cast<float4*>(dstFext)
            : reinterpret_cast<float4*>(g_scratch + dstFOff);
        dstF[(size_t)row * 32 + tx * 2]     = make_float4(a0, a1, a2, a3);
        dstF[(size_t)row * 32 + tx * 2 + 1] = make_float4(a4, a5, a6, a7);
    }
    if (OUT_H) {
        uint4* dstH = reinterpret_cast<uint4*>(g_scratch + dstHOff);
        __half2 h0 = __floats2half2_rn(a0, a1);
        __half2 h1 = __floats2half2_rn(a2, a3);
        __half2 h2 = __floats2half2_rn(a4, a5);
        __half2 h3 = __floats2half2_rn(a6, a7);
        uint4 ov;
        ov.x = *reinterpret_cast<uint32_t*>(&h0);
        ov.y = *reinterpret_cast<uint32_t*>(&h1);
        ov.z = *reinterpret_cast<uint32_t*>(&h2);
        ov.w = *reinterpret_cast<uint32_t*>(&h3);
        dstH[(size_t)row * 16 + tx] = ov;
    }
}

// ---------------------------------------------------------------------------
// fp16 mma.sync GEMM (unchanged from R9)
// ---------------------------------------------------------------------------
template<int K, int NCOLS, bool HAS_BIAS, bool HAS_ELU>
__global__ __launch_bounds__(256) void gemm_mma_kernel(
    size_t aOff, size_t wtOff, size_t cOff,
    const float* __restrict__ bias, int Mrows)
{
    constexpr int NCHUNK = K / 32;
    constexpr int RS = 40;
    __shared__ __align__(1024) __half As[2][128][RS];
    __shared__ __align__(1024) __half Bs[2][128][RS];

    const __half* __restrict__ A  = scrH(aOff);
    const __half* __restrict__ WT = scrH(wtOff);
    __half* __restrict__ C = scrH(cOff);

    int tid  = threadIdx.x;
    int lane = tid & 31;
    int warp = tid >> 5;
    int warpM = (warp & 3) * 32;
    int warpN = (warp >> 2) * 64;
    int rowBase = blockIdx.y * 128;
    int colBase = blockIdx.x * 128;

    int lrow  = tid >> 2;
    int lcol8 = tid & 3;

    float acc[2][8][4];
    #pragma unroll
    for (int mt = 0; mt < 2; mt++)
        #pragma unroll
        for (int nt = 0; nt < 8; nt++)
            #pragma unroll
            for (int r = 0; r < 4; r++)
                acc[mt][nt][r] = 0.f;

    uint32_t laneRow = lane & 15;
    uint32_t laneK   = (lane >> 4) * 8;
    uint32_t asBase = smem_u32(&As[0][0][0]);
    uint32_t bsBase = smem_u32(&Bs[0][0][0]);
    constexpr uint32_t BUFB = 128 * RS * 2;

    uint4 pa[2], pb[2];
    #pragma unroll
    for (int p = 0; p < 2; p++) {
        int row = p * 64 + lrow;
        int gm = rowBase + row;
        pa[p] = (gm < Mrows)
            ? *(const uint4*)&A[(size_t)gm * K + lcol8 * 8]
            : make_uint4(0u, 0u, 0u, 0u);
        pb[p] = *(const uint4*)&WT[(size_t)(colBase + row) * K + lcol8 * 8];
    }
    #pragma unroll
    for (int p = 0; p < 2; p++) {
        int row = p * 64 + lrow;
        *reinterpret_cast<uint4*>(&As[0][row][lcol8 * 8]) = pa[p];
        *reinterpret_cast<uint4*>(&Bs[0][row][lcol8 * 8]) = pb[p];
    }
    __syncthreads();

    for (int kc = 0; kc < NCHUNK; kc++) {
        int buf = kc & 1;
        bool more = (kc + 1 < NCHUNK);
        if (more) {
            int k0 = (kc + 1) * 32;
            #pragma unroll
            for (int p = 0; p < 2; p++) {
                int row = p * 64 + lrow;
                int gm = rowBase + row;
                pa[p] = (gm < Mrows)
                    ? *(const uint4*)&A[(size_t)gm * K + k0 + lcol8 * 8]
                    : make_uint4(0u, 0u, 0u, 0u);
                pb[p] = *(const uint4*)&WT[(size_t)(colBase + row) * K + k0 + lcol8 * 8];
            }
        }

        uint32_t aBufBase = asBase + (uint32_t)buf * BUFB;
        uint32_t bBufBase = bsBase + (uint32_t)buf * BUFB;
        #pragma unroll
        for (int ks = 0; ks < 2; ks++) {
            uint32_t k0 = ks * 16 + laneK;
            uint32_t af[2][4];
            #pragma unroll
            for (int mt = 0; mt < 2; mt++) {
                uint32_t addr = aBufBase +
                    ((warpM + mt * 16 + laneRow) * RS + k0) * 2;
                ldsm_x4(af[mt][0], af[mt][1], af[mt][2], af[mt][3], addr);
            }
            #pragma unroll
            for (int ng = 0; ng < 4; ng++) {
                uint32_t addr = bBufBase +
                    ((warpN + ng * 16 + laneRow) * RS + k0) * 2;
                uint32_t b0, b1, b2, b3;
                ldsm_x4(b0, b1, b2, b3, addr);
                #pragma unroll
                for (int mt = 0; mt < 2; mt++) {
                    mma16816(acc[mt][ng * 2],     af[mt], b0, b2);
                    mma16816(acc[mt][ng * 2 + 1], af[mt], b1, b3);
                }
            }
        }

        if (more) {
            int nb = buf ^ 1;
            #pragma unroll
            for (int p = 0; p < 2; p++) {
                int row = p * 64 + lrow;
                *reinterpret_cast<uint4*>(&As[nb][row][lcol8 * 8]) = pa[p];
                *reinterpret_cast<uint4*>(&Bs[nb][row][lcol8 * 8]) = pb[p];
            }
        }
        __syncthreads();
    }

    #pragma unroll
    for (int nt = 0; nt < 8; nt++) {
        int c = colBase + warpN + nt * 8 + (lane & 3) * 2;
        float b0 = 0.f, b1 = 0.f;
        if (HAS_BIAS) {
            b0 = __ldg(&bias[c]);
            b1 = __ldg(&bias[c + 1]);
        }
        #pragma unroll
        for (int mt = 0; mt < 2; mt++) {
            int r = rowBase + warpM + mt * 16 + (lane >> 2);
            float v0 = acc[mt][nt][0] + b0;
            float v1 = acc[mt][nt][1] + b1;
            float v2 = acc[mt][nt][2] + b0;
            float v3 = acc[mt][nt][3] + b1;
            if (HAS_ELU) {
                v0 = (v0 > 0.f) ? v0 : expm1f(v0);
                v1 = (v1 > 0.f) ? v1 : expm1f(v1);
                v2 = (v2 > 0.f) ? v2 : expm1f(v2);
                v3 = (v3 > 0.f) ? v3 : expm1f(v3);
            }
            if (r < Mrows) {
                __half2 h = __floats2half2_rn(v0, v1);
                *reinterpret_cast<uint32_t*>(&C[(size_t)r * NCOLS + c]) =
                    *reinterpret_cast<uint32_t*>(&h);
            }
            if (r + 8 < Mrows) {
                __half2 h = __floats2half2_rn(v2, v3);
                *reinterpret_cast<uint32_t*>(&C[(size_t)(r + 8) * NCOLS + c]) =
                    *reinterpret_cast<uint32_t*>(&h);
            }
        }
    }
}

// ---------------------------------------------------------------------------
// Launch: kernel launches ONLY.
// ---------------------------------------------------------------------------
extern "C" void kernel_launch(void* const* d_in, const int* in_sizes, int n_in,
                              void* d_out, int out_size)
{
    const float* x        = (const float*)d_in[0];
    const float* W1       = (const float*)d_in[1];
    const float* b1       = (const float*)d_in[2];
    const float* W2       = (const float*)d_in[3];
    const float* b2       = (const float*)d_in[4];
    const int*   node_idx = (const int*)d_in[5];
    const int*   edge_idx = (const int*)d_in[6];

    float* out   = (float*)d_out;
    float* e_out = out + (size_t)NN * F_OUT;

    // ---- CSR build + prep ----
    zero_deg_kernel<<<(NN + 255) / 256, 256>>>();
    conv_f2h_kernel<<<1024, 256>>>((const float4*)x);
    prep_wt_kernel<<<(HIDC * F_IN + 255) / 256, 256>>>(W1, W2);
    count_deg_kernel<<<2048, 256>>>(node_idx, edge_idx);
    scanA_kernel<<<NBLK_T, 256>>>();
    scanB_kernel<<<1, 128>>>();
    scanC_kernel<<<NBLK_T, 256>>>();
    fill_csr_kernel<<<2048, 256>>>(node_idx, edge_idx);

    dim3 gblk(16, 16);

    // ---- Layer 1 (GEMM commuted past both segment-sums) ----
    gather_h_kernel<false, false, true><<<(MM + 15) / 16, gblk>>>(
        OFF_XH, nullptr, 0, OFF_T1H,
        OFF_OFFM, OFF_DEGM, OFF_EN, OFF_BINV, nullptr, MM);
    gather_h_kernel<false, false, true><<<(NN + 15) / 16, gblk>>>(
        OFF_T1H, nullptr, 0, OFF_T2H,
        OFF_OFFN, OFF_DEGN, OFF_NE, OFF_DINV, nullptr, NN);
    // hh = elu(t2h @ W1 + b1)   fp16 out
    {
        dim3 grid(HIDC / 128, (NN + 127) / 128);
        gemm_mma_kernel<F_IN, HIDC, true, true><<<grid, 256>>>(
            OFF_T2H, OFF_WT1, OFF_HH, b1, NN);
    }

    // ---- Layer 2 ----
    // x2h = hh @ W2   fp16 out
    {
        dim3 grid(F_OUT / 128, (NN + 127) / 128);
        gemm_mma_kernel<HIDC, F_OUT, false, false><<<grid, 256>>>(
            OFF_HH, OFF_WT2, OFF_X2H, nullptr, NN);
    }
    // e_out[m] (fp32, returned) + eh[m] (fp16 copy)
    gather_h_kernel<false, true, true><<<(MM + 15) / 16, gblk>>>(
        OFF_X2H, e_out, 0, OFF_EH,
        OFF_OFFM, OFF_DEGM, OFF_EN, OFF_BINV, nullptr, MM);
    // out[n] = Dinv[n] * sum eh[m] + b2
    gather_h_kernel<true, true, false><<<(NN + 15) / 16, gblk>>>(
        OFF_EH, out, 0, 0,
        OFF_OFFN, OFF_DEGN, OFF_NE, OFF_DINV, b2, NN);
}

// round 11
// speedup vs baseline: 2.8339x; 1.0133x over previous
#include <cuda_runtime.h>
#include <cuda_fp16.h>
#include <cstdint>

#define NN   50000
#define MM   25000
#define NNZV 800000
#define F_IN 128
#define HIDC 256
#define F_OUT 128

// ---------------------------------------------------------------------------
// Scratch (fp16 activation chain end-to-end)
// ---------------------------------------------------------------------------
constexpr size_t SZ_XH   = (size_t)NN * F_IN * 2;
constexpr size_t SZ_T1H  = (size_t)MM * F_IN * 2;
constexpr size_t SZ_T2H  = (size_t)NN * F_IN * 2;
constexpr size_t SZ_HH   = (size_t)NN * HIDC * 2;
constexpr size_t SZ_X2H  = (size_t)NN * F_OUT * 2;
constexpr size_t SZ_EH   = (size_t)MM * F_OUT * 2;
constexpr size_t SZ_WT1  = (size_t)HIDC * F_IN * 2;
constexpr size_t SZ_WT2  = (size_t)F_OUT * HIDC * 2;
constexpr size_t SZ_DEGN = (size_t)NN * 4;
constexpr size_t SZ_DEGM = (size_t)MM * 4;
constexpr size_t SZ_OFFN = (size_t)NN * 4;
constexpr size_t SZ_OFFM = (size_t)MM * 4;
constexpr size_t SZ_DINV = (size_t)NN * 4;
constexpr size_t SZ_BINV = (size_t)MM * 4;
constexpr size_t SZ_NE   = (size_t)NNZV * 4;
constexpr size_t SZ_EN   = (size_t)NNZV * 4;
constexpr size_t SZ_RKN  = (size_t)NNZV * 4;
constexpr size_t SZ_RKM  = (size_t)NNZV * 4;
constexpr size_t SZ_BS   = 256 * 4;
constexpr size_t SZ_BP   = 256 * 4;

constexpr size_t OFF_XH   = 0;
constexpr size_t OFF_T1H  = OFF_XH + SZ_XH;
constexpr size_t OFF_T2H  = OFF_T1H + SZ_T1H;
constexpr size_t OFF_HH   = OFF_T2H + SZ_T2H;
constexpr size_t OFF_X2H  = OFF_HH + SZ_HH;
constexpr size_t OFF_EH   = OFF_X2H + SZ_X2H;
constexpr size_t OFF_WT1  = OFF_EH + SZ_EH;
constexpr size_t OFF_WT2  = OFF_WT1 + SZ_WT1;
constexpr size_t OFF_DEGN = OFF_WT2 + SZ_WT2;
constexpr size_t OFF_DEGM = OFF_DEGN + SZ_DEGN;
constexpr size_t OFF_OFFN = OFF_DEGM + SZ_DEGM;
constexpr size_t OFF_OFFM = OFF_OFFN + SZ_OFFN;
constexpr size_t OFF_DINV = OFF_OFFM + SZ_OFFM;
constexpr size_t OFF_BINV = OFF_DINV + SZ_DINV;
constexpr size_t OFF_NE   = OFF_BINV + SZ_BINV;
constexpr size_t OFF_EN   = OFF_NE + SZ_NE;
constexpr size_t OFF_RKN  = OFF_EN + SZ_EN;
constexpr size_t OFF_RKM  = OFF_RKN + SZ_RKN;
constexpr size_t OFF_BS   = OFF_RKM + SZ_RKM;
constexpr size_t OFF_BP   = OFF_BS + SZ_BS;
constexpr size_t SCRATCH_TOTAL = OFF_BP + SZ_BP;

__device__ __align__(256) unsigned char g_scratch[SCRATCH_TOTAL];

__device__ __forceinline__ float* scrF(size_t off) {
    return reinterpret_cast<float*>(g_scratch + off);
}
__device__ __forceinline__ int* scrI(size_t off) {
    return reinterpret_cast<int*>(g_scratch + off);
}
__device__ __forceinline__ __half* scrH(size_t off) {
    return reinterpret_cast<__half*>(g_scratch + off);
}

__device__ __forceinline__ uint32_t smem_u32(const void* p) {
    uint32_t a;
    asm("{ .reg .u64 t; cvta.to.shared.u64 t, %1; cvt.u32.u64 %0, t; }"
        : "=r"(a) : "l"(p));
    return a;
}
__device__ __forceinline__ void ldsm_x4(uint32_t& r0, uint32_t& r1,
                                        uint32_t& r2, uint32_t& r3,
                                        uint32_t addr) {
    asm volatile("ldmatrix.sync.aligned.m8n8.x4.shared.b16 {%0,%1,%2,%3}, [%4];"
                 : "=r"(r0), "=r"(r1), "=r"(r2), "=r"(r3) : "r"(addr));
}
__device__ __forceinline__ void mma16816(float* c, const uint32_t* a,
                                         uint32_t b0, uint32_t b1) {
    asm volatile(
        "mma.sync.aligned.m16n8k16.row.col.f32.f16.f16.f32 "
        "{%0,%1,%2,%3}, {%4,%5,%6,%7}, {%8,%9}, {%0,%1,%2,%3};"
        : "+f"(c[0]), "+f"(c[1]), "+f"(c[2]), "+f"(c[3])
        : "r"(a[0]), "r"(a[1]), "r"(a[2]), "r"(a[3]), "r"(b0), "r"(b1));
}

// ---------------------------------------------------------------------------
// CSR build
// ---------------------------------------------------------------------------
__global__ void zero_deg_kernel() {
    int i = blockIdx.x * blockDim.x + threadIdx.x;
    int* degN = scrI(OFF_DEGN);
    int* degM = scrI(OFF_DEGM);
    if (i < NN) degN[i] = 0;
    if (i < MM) degM[i] = 0;
}

__global__ void count_deg_kernel(const int* __restrict__ node_idx,
                                 const int* __restrict__ edge_idx) {
    int* degN = scrI(OFF_DEGN);
    int* degM = scrI(OFF_DEGM);
    int* rkN  = scrI(OFF_RKN);
    int* rkM  = scrI(OFF_RKM);
    int stride = gridDim.x * blockDim.x;
    for (int i = blockIdx.x * blockDim.x + threadIdx.x; i < NNZV; i += stride) {
        rkN[i] = atomicAdd(&degN[node_idx[i]], 1);
        rkM[i] = atomicAdd(&degM[edge_idx[i]], 1);
    }
}

constexpr int SC_ELEMS = 1024;
constexpr int NBLK_N = (NN + SC_ELEMS - 1) / SC_ELEMS;   // 49
constexpr int NBLK_M = (MM + SC_ELEMS - 1) / SC_ELEMS;   // 25
constexpr int NBLK_T = NBLK_N + NBLK_M;                  // 74

__global__ __launch_bounds__(256) void scanA_kernel() {
    int blk = blockIdx.x;
    const int* deg;
    int n, b;
    if (blk < NBLK_N) { deg = scrI(OFF_DEGN); n = NN; b = blk; }
    else              { deg = scrI(OFF_DEGM); n = MM; b = blk - NBLK_N; }
    int tid = threadIdx.x;
    int base = b * SC_ELEMS + tid * 4;
    int s = 0;
    #pragma unroll
    for (int j = 0; j < 4; j++) {
        int i = base + j;
        if (i < n) s += deg[i];
    }
    __shared__ int wsum[8];
    for (int d2 = 16; d2 > 0; d2 >>= 1) s += __shfl_down_sync(0xffffffffu, s, d2);
    if ((tid & 31) == 0) wsum[tid >> 5] = s;
    __syncthreads();
    if (tid < 8) {
        int v = wsum[tid];
        for (int d2 = 4; d2 > 0; d2 >>= 1) v += __shfl_down_sync(0xffu, v, d2);
        if (tid == 0) scrI(OFF_BS)[blk] = v;
    }
}

__global__ void scanB_kernel() {
    __shared__ int sh[128];
    int tid = threadIdx.x;
    const int* bs = scrI(OFF_BS);
    sh[tid] = (tid < NBLK_T) ? bs[tid] : 0;
    __syncthreads();
    for (int d = 1; d < 128; d <<= 1) {
        int v = (tid >= d) ? sh[tid - d] : 0;
        __syncthreads();
        sh[tid] += v;
        __syncthreads();
    }
    if (tid < NBLK_T) {
        int pre = (tid == 0) ? 0 : sh[tid - 1];
        if (tid >= NBLK_N) pre -= sh[NBLK_N - 1];
        scrI(OFF_BP)[tid] = pre;
    }
}

__global__ __launch_bounds__(256) void scanC_kernel() {
    int blk = blockIdx.x;
    const int* deg; int* off; float* inv;
    int n, b;
    if (blk < NBLK_N) {
        deg = scrI(OFF_DEGN); off = scrI(OFF_OFFN);
        inv = scrF(OFF_DINV); n = NN; b = blk;
    } else {
        deg = scrI(OFF_DEGM); off = scrI(OFF_OFFM);
        inv = scrF(OFF_BINV); n = MM; b = blk - NBLK_N;
    }
    int tid = threadIdx.x;
    int base = b * SC_ELEMS + tid * 4;
    int d[4];
    int s = 0;
    #pragma unroll
    for (int j = 0; j < 4; j++) {
        int i = base + j;
        d[j] = (i < n) ? deg[i] : 0;
        s += d[j];
    }
    __shared__ int sh[256];
    sh[tid] = s;
    __syncthreads();
    for (int dd = 1; dd < 256; dd <<= 1) {
        int v = (tid >= dd) ? sh[tid - dd] : 0;
        __syncthreads();
        sh[tid] += v;
        __syncthreads();
    }
    int run = scrI(OFF_BP)[blk] + ((tid == 0) ? 0 : sh[tid - 1]);
    #pragma unroll
    for (int j = 0; j < 4; j++) {
        int i = base + j;
        if (i < n) {
            off[i] = run;
            inv[i] = (d[j] > 0) ? (1.0f / (float)d[j]) : 0.0f;
            run += d[j];
        }
    }
}

__global__ void fill_csr_kernel(const int* __restrict__ node_idx,
                                const int* __restrict__ edge_idx) {
    const int* offN = scrI(OFF_OFFN);
    const int* offM = scrI(OFF_OFFM);
    const int* rkN  = scrI(OFF_RKN);
    const int* rkM  = scrI(OFF_RKM);
    int* nodeEdges = scrI(OFF_NE);
    int* edgeNodes = scrI(OFF_EN);
    int stride = gridDim.x * blockDim.x;
    for (int i = blockIdx.x * blockDim.x + threadIdx.x; i < NNZV; i += stride) {
        int n = node_idx[i];
        int m = edge_idx[i];
        nodeEdges[offN[n] + rkN[i]] = m;
        edgeNodes[offM[m] + rkM[i]] = n;
    }
}

// ---------------------------------------------------------------------------
// Prep: x fp32 -> fp16; W1/W2 -> K-major fp16 transposes
// ---------------------------------------------------------------------------
__global__ __launch_bounds__(256) void conv_f2h_kernel(const float4* __restrict__ x) {
    uint2* xh = reinterpret_cast<uint2*>(g_scratch + OFF_XH);
    int stride = gridDim.x * blockDim.x;
    for (int i = blockIdx.x * blockDim.x + threadIdx.x; i < NN * 32; i += stride) {
        float4 v = __ldg(&x[i]);
        __half2 h01 = __floats2half2_rn(v.x, v.y);
        __half2 h23 = __floats2half2_rn(v.z, v.w);
        uint2 o;
        o.x = *reinterpret_cast<uint32_t*>(&h01);
        o.y = *reinterpret_cast<uint32_t*>(&h23);
        xh[i] = o;
    }
}

__global__ __launch_bounds__(256) void prep_wt_kernel(
    const float* __restrict__ W1, const float* __restrict__ W2)
{
    int i = blockIdx.x * blockDim.x + threadIdx.x;
    __half* wt1 = scrH(OFF_WT1);
    __half* wt2 = scrH(OFF_WT2);
    if (i < HIDC * F_IN) {
        int n = i / F_IN, k = i % F_IN;
        wt1[i] = __float2half(W1[k * HIDC + n]);
    }
    if (i < F_OUT * HIDC) {
        int n = i / HIDC, k = i % HIDC;
        wt2[i] = __float2half(W2[k * F_OUT + n]);
    }
}

// ---------------------------------------------------------------------------
// Gather-reduce over fp16 sources (C = 128). One WARP per row, split halves:
// lanes 0-15 take even-j neighbors, lanes 16-31 odd-j; each lane loads the
// uint4 column (lane&15). Halves combined with shfl_xor(16) at the end.
// Index loads stay half-warp-uniform (L1 broadcast). Unroll-8 per half.
// ---------------------------------------------------------------------------
template<bool HAS_BIAS, bool OUT_F, bool OUT_H>
__global__ void gather_h_kernel(size_t srcOff,
                                float* dstFext, size_t dstFOff,
                                size_t dstHOff,
                                size_t offOff, size_t degOff,
                                size_t lstOff, size_t invOff,
                                const float* __restrict__ bias,
                                int nrows)
{
    const uint4* __restrict__ src =
        reinterpret_cast<const uint4*>(g_scratch + srcOff);
    const int* __restrict__ off = scrI(offOff);
    const int* __restrict__ deg = scrI(degOff);
    const int* __restrict__ lst = scrI(lstOff);
    const float* __restrict__ inv = scrF(invOff);

    int row = blockIdx.x * blockDim.y + threadIdx.y;
    if (row >= nrows) return;
    int lane = threadIdx.x;        // 0..31
    int half = lane >> 4;          // 0 or 1
    int tx   = lane & 15;          // uint4 column
    int o = off[row];
    int d = deg[row];

    float a0 = 0.f, a1 = 0.f, a2 = 0.f, a3 = 0.f;
    float a4 = 0.f, a5 = 0.f, a6 = 0.f, a7 = 0.f;

    // Half `half` handles j = half, half+2, half+4, ...
    int j = half;
    // unroll-8 per half: covers j, j+2, ..., j+14
    for (; j + 14 < d; j += 16) {
        int idx[8];
        #pragma unroll
        for (int q = 0; q < 8; q++) idx[q] = __ldg(&lst[o + j + 2 * q]);
        uint4 v[8];
        #pragma unroll
        for (int q = 0; q < 8; q++) v[q] = __ldg(&src[(size_t)idx[q] * 16 + tx]);
        #pragma unroll
        for (int q = 0; q < 8; q++) {
            float2 f;
            f = __half22float2(*reinterpret_cast<__half2*>(&v[q].x)); a0 += f.x; a1 += f.y;
            f = __half22float2(*reinterpret_cast<__half2*>(&v[q].y)); a2 += f.x; a3 += f.y;
            f = __half22float2(*reinterpret_cast<__half2*>(&v[q].z)); a4 += f.x; a5 += f.y;
            f = __half22float2(*reinterpret_cast<__half2*>(&v[q].w)); a6 += f.x; a7 += f.y;
        }
    }
    // unroll-4 tail per half: covers j..j+6
    if (j + 6 < d) {
        int idx[4];
        #pragma unroll
        for (int q = 0; q < 4; q++) idx[q] = __ldg(&lst[o + j + 2 * q]);
        uint4 v[4];
        #pragma unroll
        for (int q = 0; q < 4; q++) v[q] = __ldg(&src[(size_t)idx[q] * 16 + tx]);
        #pragma unroll
        for (int q = 0; q < 4; q++) {
            float2 f;
            f = __half22float2(*reinterpret_cast<__half2*>(&v[q].x)); a0 += f.x; a1 += f.y;
            f = __half22float2(*reinterpret_cast<__half2*>(&v[q].y)); a2 += f.x; a3 += f.y;
            f = __half22float2(*reinterpret_cast<__half2*>(&v[q].z)); a4 += f.x; a5 += f.y;
            f = __half22float2(*reinterpret_cast<__half2*>(&v[q].w)); a6 += f.x; a7 += f.y;
        }
        j += 8;
    }
    for (; j < d; j += 2) {
        int i0 = __ldg(&lst[o + j]);
        uint4 v0 = __ldg(&src[(size_t)i0 * 16 + tx]);
        float2 f;
        f = __half22float2(*reinterpret_cast<__half2*>(&v0.x)); a0 += f.x; a1 += f.y;
        f = __half22float2(*reinterpret_cast<__half2*>(&v0.y)); a2 += f.x; a3 += f.y;
        f = __half22float2(*reinterpret_cast<__half2*>(&v0.z)); a4 += f.x; a5 += f.y;
        f = __half22float2(*reinterpret_cast<__half2*>(&v0.w)); a6 += f.x; a7 += f.y;
    }

    // combine the two halves (lane <-> lane^16 hold partial sums of same cols)
    a0 += __shfl_xor_sync(0xffffffffu, a0, 16);
    a1 += __shfl_xor_sync(0xffffffffu, a1, 16);
    a2 += __shfl_xor_sync(0xffffffffu, a2, 16);
    a3 += __shfl_xor_sync(0xffffffffu, a3, 16);
    a4 += __shfl_xor_sync(0xffffffffu, a4, 16);
    a5 += __shfl_xor_sync(0xffffffffu, a5, 16);
    a6 += __shfl_xor_sync(0xffffffffu, a6, 16);
    a7 += __shfl_xor_sync(0xffffffffu, a7, 16);

    if (half != 0) return;   // lanes 0-15 finish up

    float s = inv[row];
    a0 *= s; a1 *= s; a2 *= s; a3 *= s;
    a4 *= s; a5 *= s; a6 *= s; a7 *= s;
    if (HAS_BIAS) {
        const float4* b4 = reinterpret_cast<const float4*>(bias);
        float4 b0 = __ldg(&b4[tx * 2]);
        float4 b1 = __ldg(&b4[tx * 2 + 1]);
        a0 += b0.x; a1 += b0.y; a2 += b0.z; a3 += b0.w;
        a4 += b1.x; a5 += b1.y; a6 += b1.z; a7 += b1.w;
    }
    if (OUT_F) {
        float4* dstF = dstFext
            ? reinterpret_cast<float4*>(dstFext)
            : reinterpret_cast<float4*>(g_scratch + dstFOff);
        dstF[(size_t)row * 32 + tx * 2]     = make_float4(a0, a1, a2, a3);
        dstF[(size_t)row * 32 + tx * 2 + 1] = make_float4(a4, a5, a6, a7);
    }
    if (OUT_H) {
        uint4* dstH = reinterpret_cast<uint4*>(g_scratch + dstHOff);
        __half2 h0 = __floats2half2_rn(a0, a1);
        __half2 h1 = __floats2half2_rn(a2, a3);
        __half2 h2 = __floats2half2_rn(a4, a5);
        __half2 h3 = __floats2half2_rn(a6, a7);
        uint4 ov;
        ov.x = *reinterpret_cast<uint32_t*>(&h0);
        ov.y = *reinterpret_cast<uint32_t*>(&h1);
        ov.z = *reinterpret_cast<uint32_t*>(&h2);
        ov.w = *reinterpret_cast<uint32_t*>(&h3);
        dstH[(size_t)row * 16 + tx] = ov;
    }
}

// ---------------------------------------------------------------------------
// fp16 mma.sync GEMM (unchanged from R9/R10)
// ---------------------------------------------------------------------------
template<int K, int NCOLS, bool HAS_BIAS, bool HAS_ELU>
__global__ __launch_bounds__(256) void gemm_mma_kernel(
    size_t aOff, size_t wtOff, size_t cOff,
    const float* __restrict__ bias, int Mrows)
{
    constexpr int NCHUNK = K / 32;
    constexpr int RS = 40;
    __shared__ __align__(1024) __half As[2][128][RS];
    __shared__ __align__(1024) __half Bs[2][128][RS];

    const __half* __restrict__ A  = scrH(aOff);
    const __half* __restrict__ WT = scrH(wtOff);
    __half* __restrict__ C = scrH(cOff);

    int tid  = threadIdx.x;
    int lane = tid & 31;
    int warp = tid >> 5;
    int warpM = (warp & 3) * 32;
    int warpN = (warp >> 2) * 64;
    int rowBase = blockIdx.y * 128;
    int colBase = blockIdx.x * 128;

    int lrow  = tid >> 2;
    int lcol8 = tid & 3;

    float acc[2][8][4];
    #pragma unroll
    for (int mt = 0; mt < 2; mt++)
        #pragma unroll
        for (int nt = 0; nt < 8; nt++)
            #pragma unroll
            for (int r = 0; r < 4; r++)
                acc[mt][nt][r] = 0.f;

    uint32_t laneRow = lane & 15;
    uint32_t laneK   = (lane >> 4) * 8;
    uint32_t asBase = smem_u32(&As[0][0][0]);
    uint32_t bsBase = smem_u32(&Bs[0][0][0]);
    constexpr uint32_t BUFB = 128 * RS * 2;

    uint4 pa[2], pb[2];
    #pragma unroll
    for (int p = 0; p < 2; p++) {
        int row = p * 64 + lrow;
        int gm = rowBase + row;
        pa[p] = (gm < Mrows)
            ? *(const uint4*)&A[(size_t)gm * K + lcol8 * 8]
            : make_uint4(0u, 0u, 0u, 0u);
        pb[p] = *(const uint4*)&WT[(size_t)(colBase + row) * K + lcol8 * 8];
    }
    #pragma unroll
    for (int p = 0; p < 2; p++) {
        int row = p * 64 + lrow;
        *reinterpret_cast<uint4*>(&As[0][row][lcol8 * 8]) = pa[p];
        *reinterpret_cast<uint4*>(&Bs[0][row][lcol8 * 8]) = pb[p];
    }
    __syncthreads();

    for (int kc = 0; kc < NCHUNK; kc++) {
        int buf = kc & 1;
        bool more = (kc + 1 < NCHUNK);
        if (more) {
            int k0 = (kc + 1) * 32;
            #pragma unroll
            for (int p = 0; p < 2; p++) {
                int row = p * 64 + lrow;
                int gm = rowBase + row;
                pa[p] = (gm < Mrows)
                    ? *(const uint4*)&A[(size_t)gm * K + k0 + lcol8 * 8]
                    : make_uint4(0u, 0u, 0u, 0u);
                pb[p] = *(const uint4*)&WT[(size_t)(colBase + row) * K + k0 + lcol8 * 8];
            }
        }

        uint32_t aBufBase = asBase + (uint32_t)buf * BUFB;
        uint32_t bBufBase = bsBase + (uint32_t)buf * BUFB;
        #pragma unroll
        for (int ks = 0; ks < 2; ks++) {
            uint32_t k0 = ks * 16 + laneK;
            uint32_t af[2][4];
            #pragma unroll
            for (int mt = 0; mt < 2; mt++) {
                uint32_t addr = aBufBase +
                    ((warpM + mt * 16 + laneRow) * RS + k0) * 2;
                ldsm_x4(af[mt][0], af[mt][1], af[mt][2], af[mt][3], addr);
            }
            #pragma unroll
            for (int ng = 0; ng < 4; ng++) {
                uint32_t addr = bBufBase +
                    ((warpN + ng * 16 + laneRow) * RS + k0) * 2;
                uint32_t b0, b1, b2, b3;
                ldsm_x4(b0, b1, b2, b3, addr);
                #pragma unroll
                for (int mt = 0; mt < 2; mt++) {
                    mma16816(acc[mt][ng * 2],     af[mt], b0, b2);
                    mma16816(acc[mt][ng * 2 + 1], af[mt], b1, b3);
                }
            }
        }

        if (more) {
            int nb = buf ^ 1;
            #pragma unroll
            for (int p = 0; p < 2; p++) {
                int row = p * 64 + lrow;
                *reinterpret_cast<uint4*>(&As[nb][row][lcol8 * 8]) = pa[p];
                *reinterpret_cast<uint4*>(&Bs[nb][row][lcol8 * 8]) = pb[p];
            }
        }
        __syncthreads();
    }

    #pragma unroll
    for (int nt = 0; nt < 8; nt++) {
        int c = colBase + warpN + nt * 8 + (lane & 3) * 2;
        float b0 = 0.f, b1 = 0.f;
        if (HAS_BIAS) {
            b0 = __ldg(&bias[c]);
            b1 = __ldg(&bias[c + 1]);
        }
        #pragma unroll
        for (int mt = 0; mt < 2; mt++) {
            int r = rowBase + warpM + mt * 16 + (lane >> 2);
            float v0 = acc[mt][nt][0] + b0;
            float v1 = acc[mt][nt][1] + b1;
            float v2 = acc[mt][nt][2] + b0;
            float v3 = acc[mt][nt][3] + b1;
            if (HAS_ELU) {
                v0 = (v0 > 0.f) ? v0 : expm1f(v0);
                v1 = (v1 > 0.f) ? v1 : expm1f(v1);
                v2 = (v2 > 0.f) ? v2 : expm1f(v2);
                v3 = (v3 > 0.f) ? v3 : expm1f(v3);
            }
            if (r < Mrows) {
                __half2 h = __floats2half2_rn(v0, v1);
                *reinterpret_cast<uint32_t*>(&C[(size_t)r * NCOLS + c]) =
                    *reinterpret_cast<uint32_t*>(&h);
            }
            if (r + 8 < Mrows) {
                __half2 h = __floats2half2_rn(v2, v3);
                *reinterpret_cast<uint32_t*>(&C[(size_t)(r + 8) * NCOLS + c]) =
                    *reinterpret_cast<uint32_t*>(&h);
            }
        }
    }
}

// ---------------------------------------------------------------------------
// Launch: kernel launches ONLY.
// ---------------------------------------------------------------------------
extern "C" void kernel_launch(void* const* d_in, const int* in_sizes, int n_in,
                              void* d_out, int out_size)
{
    const float* x        = (const float*)d_in[0];
    const float* W1       = (const float*)d_in[1];
    const float* b1       = (const float*)d_in[2];
    const float* W2       = (const float*)d_in[3];
    const float* b2       = (const float*)d_in[4];
    const int*   node_idx = (const int*)d_in[5];
    const int*   edge_idx = (const int*)d_in[6];

    float* out   = (float*)d_out;
    float* e_out = out + (size_t)NN * F_OUT;

    // ---- CSR build + prep ----
    zero_deg_kernel<<<(NN + 255) / 256, 256>>>();
    conv_f2h_kernel<<<1024, 256>>>((const float4*)x);
    prep_wt_kernel<<<(HIDC * F_IN + 255) / 256, 256>>>(W1, W2);
    count_deg_kernel<<<2048, 256>>>(node_idx, edge_idx);
    scanA_kernel<<<NBLK_T, 256>>>();
    scanB_kernel<<<1, 128>>>();
    scanC_kernel<<<NBLK_T, 256>>>();
    fill_csr_kernel<<<2048, 256>>>(node_idx, edge_idx);

    dim3 gblk(32, 8);   // 256 threads, one warp per row, 8 rows/block

    // ---- Layer 1 (GEMM commuted past both segment-sums) ----
    gather_h_kernel<false, false, true><<<(MM + 7) / 8, gblk>>>(
        OFF_XH, nullptr, 0, OFF_T1H,
        OFF_OFFM, OFF_DEGM, OFF_EN, OFF_BINV, nullptr, MM);
    gather_h_kernel<false, false, true><<<(NN + 7) / 8, gblk>>>(
        OFF_T1H, nullptr, 0, OFF_T2H,
        OFF_OFFN, OFF_DEGN, OFF_NE, OFF_DINV, nullptr, NN);
    // hh = elu(t2h @ W1 + b1)   fp16 out
    {
        dim3 grid(HIDC / 128, (NN + 127) / 128);
        gemm_mma_kernel<F_IN, HIDC, true, true><<<grid, 256>>>(
            OFF_T2H, OFF_WT1, OFF_HH, b1, NN);
    }

    // ---- Layer 2 ----
    // x2h = hh @ W2   fp16 out
    {
        dim3 grid(F_OUT / 128, (NN + 127) / 128);
        gemm_mma_kernel<HIDC, F_OUT, false, false><<<grid, 256>>>(
            OFF_HH, OFF_WT2, OFF_X2H, nullptr, NN);
    }
    // e_out[m] (fp32, returned) + eh[m] (fp16 copy)
    gather_h_kernel<false, true, true><<<(MM + 7) / 8, gblk>>>(
        OFF_X2H, e_out, 0, OFF_EH,
        OFF_OFFM, OFF_DEGM, OFF_EN, OFF_BINV, nullptr, MM);
    // out[n] = Dinv[n] * sum eh[m] + b2
    gather_h_kernel<true, true, false><<<(NN + 7) / 8, gblk>>>(
        OFF_EH, out, 0, 0,
        OFF_OFFN, OFF_DEGN, OFF_NE, OFF_DINV, b2, NN);
}